// round 8
// baseline (speedup 1.0000x reference)
#include <cuda_runtime.h>
#include <cuda_fp16.h>
#include <math.h>
#include <stdint.h>

#define N_TOK 8192
#define D_DIM 1024
#define E_NUM 8
#define H_DIM 4096
#define CAP   8192
#define PAIRS 16384

#define TM 128
#define TK 64              // fp16 elems per k-chunk (128 bytes per row)
#define ROWB 144           // padded SMEM row bytes (128 data + 16 pad)
#define NSTAGE 3

// ---------------- device scratch ----------------
__device__ int   g_cnt[E_NUM];
__device__ int   g_off[E_NUM];
__device__ int   g_tok[E_NUM * CAP];
__device__ int   g_tslot[2 * N_TOK];
__device__ float g_tw  [2 * N_TOK];

__device__ __half g_xh[(size_t)N_TOK * D_DIM];
__device__ __half g_xl[(size_t)N_TOK * D_DIM];
__device__ __half g_hh[(size_t)PAIRS * H_DIM];
__device__ __half g_hl[(size_t)PAIRS * H_DIM];
__device__ float  g_y [(size_t)PAIRS * D_DIM];
__device__ __half g_B1h[(size_t)E_NUM * H_DIM * D_DIM];
__device__ __half g_B2h[(size_t)E_NUM * D_DIM * H_DIM];

// ---------------- helpers ----------------
__device__ __forceinline__ uint32_t smem_u32(const void* p) {
    return (uint32_t)__cvta_generic_to_shared(p);
}
#define CP16(dst, src) \
    asm volatile("cp.async.cg.shared.global [%0], [%1], 16;" :: "r"(dst), "l"(src) : "memory")
#define CP_COMMIT() asm volatile("cp.async.commit_group;" ::: "memory")

__device__ __forceinline__ void ldsm4(uint32_t* r, uint32_t addr) {
    asm volatile("ldmatrix.sync.aligned.m8n8.x4.shared.b16 {%0,%1,%2,%3}, [%4];"
        : "=r"(r[0]), "=r"(r[1]), "=r"(r[2]), "=r"(r[3]) : "r"(addr));
}
__device__ __forceinline__ void mma_f16(float* c, const uint32_t* a, const uint32_t* b) {
    asm volatile("mma.sync.aligned.m16n8k16.row.col.f32.f16.f16.f32 "
        "{%0,%1,%2,%3}, {%4,%5,%6,%7}, {%8,%9}, {%0,%1,%2,%3};"
        : "+f"(c[0]), "+f"(c[1]), "+f"(c[2]), "+f"(c[3])
        : "r"(a[0]), "r"(a[1]), "r"(a[2]), "r"(a[3]), "r"(b[0]), "r"(b[1]));
}

// ---------------- small kernels ----------------
__global__ void zero_cnt_kernel() {
    if (threadIdx.x < E_NUM) g_cnt[threadIdx.x] = 0;
}

__global__ void cvt_x_kernel(const float* __restrict__ x) {
    size_t stride = (size_t)gridDim.x * blockDim.x;
    size_t n = (size_t)N_TOK * D_DIM;
    for (size_t i = (size_t)blockIdx.x * blockDim.x + threadIdx.x; i < n; i += stride) {
        float v = x[i];
        __half h = __float2half_rn(v);
        g_xh[i] = h;
        g_xl[i] = __float2half_rn(v - __half2float(h));
    }
}

// W[e][K][N] fp32 -> P[e][N][K] fp16 hi (32x32 tile transpose)
__global__ __launch_bounds__(256)
void pack_w_kernel(const float* __restrict__ W, __half* __restrict__ Ph, int K, int N) {
    __shared__ float s[32][33];
    const int k0 = blockIdx.x * 32, n0 = blockIdx.y * 32, e = blockIdx.z;
    const int tid = threadIdx.x;
    const int kk = tid >> 5, nn = tid & 31;
#pragma unroll
    for (int i = 0; i < 4; i++)
        s[kk + i * 8][nn] = W[((size_t)e * K + k0 + kk + i * 8) * N + n0 + nn];
    __syncthreads();
    const int n_r = tid >> 4;
    const int kp  = (tid & 15) * 2;
#pragma unroll
    for (int i = 0; i < 2; i++) {
        int nr = n_r + i * 16;
        __half2 hp;
        hp.x = __float2half_rn(s[kp][nr]);
        hp.y = __float2half_rn(s[kp + 1][nr]);
        size_t o = ((size_t)e * N + n0 + nr) * K + k0 + kp;
        *(__half2*)(Ph + o) = hp;
    }
}

__global__ void router_kernel(const float* __restrict__ x,
                              const float* __restrict__ Wr,
                              const float* __restrict__ br) {
    int warp = (blockIdx.x * blockDim.x + threadIdx.x) >> 5;
    int lane = threadIdx.x & 31;
    if (warp >= N_TOK) return;
    const float* xr = x + (size_t)warp * D_DIM;
    float acc[8];
#pragma unroll
    for (int e = 0; e < 8; e++) acc[e] = 0.0f;
    for (int d = lane; d < D_DIM; d += 32) {
        float xv = xr[d];
        const float4* w4 = (const float4*)(Wr + (size_t)d * E_NUM);
        float4 a = w4[0], b = w4[1];
        acc[0] += xv * a.x; acc[1] += xv * a.y; acc[2] += xv * a.z; acc[3] += xv * a.w;
        acc[4] += xv * b.x; acc[5] += xv * b.y; acc[6] += xv * b.z; acc[7] += xv * b.w;
    }
#pragma unroll
    for (int off = 16; off > 0; off >>= 1)
#pragma unroll
        for (int e = 0; e < 8; e++)
            acc[e] += __shfl_down_sync(0xffffffffu, acc[e], off);
    if (lane == 0) {
        float lg[8];
#pragma unroll
        for (int e = 0; e < 8; e++) lg[e] = acc[e] + br[e];
        int e0 = 0;
#pragma unroll
        for (int e = 1; e < 8; e++) if (lg[e] > lg[e0]) e0 = e;
        int e1 = (e0 == 0) ? 1 : 0;
#pragma unroll
        for (int e = 0; e < 8; e++)
            if (e != e0 && e != e1 && lg[e] > lg[e1]) e1 = e;
        float z  = __expf(lg[e1] - lg[e0]);
        float w0 = 1.0f / (1.0f + z);
        float w1 = z * w0;
        int p0 = atomicAdd(&g_cnt[e0], 1);
        g_tok[e0 * CAP + p0] = warp;
        int p1 = atomicAdd(&g_cnt[e1], 1);
        g_tok[e1 * CAP + p1] = warp;
        g_tslot[2 * warp]     = e0 * CAP + p0;  g_tw[2 * warp]     = w0;
        g_tslot[2 * warp + 1] = e1 * CAP + p1;  g_tw[2 * warp + 1] = w1;
    }
}

__global__ void offsets_kernel() {
    if (threadIdx.x == 0 && blockIdx.x == 0) {
        int acc = 0;
#pragma unroll
        for (int e = 0; e < E_NUM; e++) { g_off[e] = acc; acc += g_cnt[e]; }
    }
}

__global__ void combine_kernel(float* __restrict__ out) {
    int i = blockIdx.x * blockDim.x + threadIdx.x;
    int t = i >> 8;
    int j = (i & 255) << 2;
    int s0e = g_tslot[2 * t], s1e = g_tslot[2 * t + 1];
    float w0 = g_tw[2 * t], w1 = g_tw[2 * t + 1];
    size_t s0 = (size_t)g_off[s0e >> 13] + (s0e & (CAP - 1));
    size_t s1 = (size_t)g_off[s1e >> 13] + (s1e & (CAP - 1));
    float4 a = *(const float4*)(g_y + s0 * D_DIM + j);
    float4 b = *(const float4*)(g_y + s1 * D_DIM + j);
    float4 o;
    o.x = w0 * a.x + w1 * b.x;
    o.y = w0 * a.y + w1 * b.y;
    o.z = w0 * a.z + w1 * b.z;
    o.w = w0 * a.w + w1 * b.w;
    *(float4*)(out + (size_t)t * D_DIM + j) = o;
}

// ---- grouped GEMM: mma.sync fp16 2-term split, TM=128 x TNV tile, TK=64 ----
template <int PHASE, int KDIM, int NDIM, int TNV>
__global__ __launch_bounds__(256, 1)
void moe_hmma(const __half* __restrict__ Ahg, const __half* __restrict__ Alg,
              const __half* __restrict__ Bhg,
              const float* __restrict__ bias) {
    constexpr int C    = KDIM / TK;
    constexpr int TNW  = TNV / 4;        // warp N tile (64 or 32)
    constexpr int NT   = TNW / 8;        // mma n-steps per warp (8 or 4)
    constexpr int NT2  = TNW / 16;       // ldsm.x4 per kk for B (4 or 2)
    constexpr int TPR  = 256 / TNV;      // threads per B row (1 or 2)
    constexpr int AHo  = 0;
    constexpr int ALo  = 128 * ROWB;
    constexpr int BHo  = 2 * 128 * ROWB;
    constexpr uint32_t STGv = BHo + TNV * ROWB;

    const int e  = blockIdx.z;
    const int Ne = g_cnt[e];
    const int m0 = blockIdx.x * TM;
    if (m0 >= Ne) return;
    const int n0 = blockIdx.y * TNV;
    const int base = g_off[e];

    extern __shared__ __align__(128) char smem[];
    const uint32_t sb = smem_u32(smem);
    const int tid = threadIdx.x;

    // ---- A loads: 128 rows, 2 threads/row, 4x16B segs each ----
    const int ar = tid >> 1;
    const int asg = (tid & 1) * 64;
    const char *ah, *al;
    {
        int rr = min(m0 + ar, Ne - 1);
        size_t i0 = (PHASE == 1) ? (size_t)g_tok[e * CAP + rr] : (size_t)(base + rr);
        ah = (const char*)(Ahg + i0 * KDIM) + asg;
        al = (const char*)(Alg + i0 * KDIM) + asg;
    }
    const uint32_t dA = (uint32_t)ar * ROWB + asg;

    // ---- B loads: TNV rows, TPR threads/row, (8/TPR) segs each ----
    const int brr = (TPR == 1) ? tid : (tid >> 1);
    const int bsg = (TPR == 1) ? 0 : (tid & 1) * 64;
    const char* bh = (const char*)(Bhg + ((size_t)e * NDIM + n0 + brr) * KDIM) + bsg;
    const uint32_t dB = (uint32_t)brr * ROWB + bsg;

    auto issue = [&](int c) {
        if (c < C) {
            uint32_t st = sb + (uint32_t)(c % NSTAGE) * STGv;
            int cb = c * 128;   // bytes per chunk along K
#pragma unroll
            for (int i = 0; i < 4; i++) {
                CP16(st + AHo + dA + i * 16, ah + cb + i * 16);
                CP16(st + ALo + dA + i * 16, al + cb + i * 16);
            }
#pragma unroll
            for (int i = 0; i < 8 / TPR; i++)
                CP16(st + BHo + dB + i * 16, bh + cb + i * 16);
        }
        CP_COMMIT();
    };

    float acc[4][NT][4];
#pragma unroll
    for (int i = 0; i < 4; i++)
#pragma unroll
        for (int j = 0; j < NT; j++)
#pragma unroll
            for (int k = 0; k < 4; k++) acc[i][j][k] = 0.0f;

    const int lane = tid & 31, wid = tid >> 5;
    const int wm = (wid & 1) * 64;
    const int wn = (wid >> 1) * TNW;
    const uint32_t a_off = (uint32_t)(wm + (lane & 15)) * ROWB + (lane >> 4) * 16;
    const uint32_t b_off = (uint32_t)(wn + (lane & 7) + ((lane >> 4) & 1) * 8) * ROWB
                         + ((lane >> 3) & 1) * 16;

    issue(0);
    issue(1);

    for (int c = 0; c < C; c++) {
        asm volatile("cp.async.wait_group 1;" ::: "memory");
        __syncthreads();
        issue(c + 2);

        const uint32_t st = sb + (uint32_t)(c % NSTAGE) * STGv;
#pragma unroll
        for (int kk = 0; kk < 4; kk++) {
            uint32_t af[16], tf[4 * NT2];
#pragma unroll
            for (int tn2 = 0; tn2 < NT2; tn2++)
                ldsm4(tf + tn2 * 4, st + BHo + b_off + tn2 * 16 * ROWB + kk * 32);
            // A hi x B hi
#pragma unroll
            for (int tm = 0; tm < 4; tm++)
                ldsm4(af + tm * 4, st + AHo + a_off + tm * 16 * ROWB + kk * 32);
#pragma unroll
            for (int tm = 0; tm < 4; tm++)
#pragma unroll
                for (int tn = 0; tn < NT; tn++)
                    mma_f16(acc[tm][tn], af + tm * 4, tf + tn * 2);
            // A lo x B hi (reuse af)
#pragma unroll
            for (int tm = 0; tm < 4; tm++)
                ldsm4(af + tm * 4, st + ALo + a_off + tm * 16 * ROWB + kk * 32);
#pragma unroll
            for (int tm = 0; tm < 4; tm++)
#pragma unroll
                for (int tn = 0; tn < NT; tn++)
                    mma_f16(acc[tm][tn], af + tm * 4, tf + tn * 2);
        }
    }

    // ---- epilogue ----
    const int lr_base  = wm + (lane >> 2);
    const int col_base = n0 + wn + 2 * (lane & 3);
    const float* bp = bias + (size_t)e * NDIM;
#pragma unroll
    for (int tm = 0; tm < 4; tm++) {
#pragma unroll
        for (int half = 0; half < 2; half++) {
            int gr = m0 + lr_base + tm * 16 + half * 8;
            if (gr < Ne) {
                size_t pr = (size_t)(base + gr);
#pragma unroll
                for (int tn = 0; tn < NT; tn++) {
                    int col = col_base + tn * 8;
                    float c0 = acc[tm][tn][half * 2 + 0] + __ldg(bp + col);
                    float c1 = acc[tm][tn][half * 2 + 1] + __ldg(bp + col + 1);
                    if (PHASE == 1) {
                        c0 = fmaxf(c0, 0.f);
                        c1 = fmaxf(c1, 0.f);
                        __half h0 = __float2half_rn(c0);
                        __half h1 = __float2half_rn(c1);
                        __half2 hp; hp.x = h0; hp.y = h1;
                        __half2 lp;
                        lp.x = __float2half_rn(c0 - __half2float(h0));
                        lp.y = __float2half_rn(c1 - __half2float(h1));
                        *(__half2*)(g_hh + pr * H_DIM + col) = hp;
                        *(__half2*)(g_hl + pr * H_DIM + col) = lp;
                    } else {
                        float2 o; o.x = c0; o.y = c1;
                        *(float2*)(g_y + pr * D_DIM + col) = o;
                    }
                }
            }
        }
    }
}

// ---------------- launch ----------------
extern "C" void kernel_launch(void* const* d_in, const int* in_sizes, int n_in,
                              void* d_out, int out_size) {
    const float* x  = (const float*)d_in[0];
    const float* Wr = (const float*)d_in[1];
    const float* br = (const float*)d_in[2];
    const float* W1 = (const float*)d_in[3];
    const float* b1 = (const float*)d_in[4];
    const float* W2 = (const float*)d_in[5];
    const float* b2 = (const float*)d_in[6];
    float* out = (float*)d_out;

    const int SMEM1 = NSTAGE * (2 * 128 * ROWB + 256 * ROWB);   // 221184
    const int SMEM2 = NSTAGE * (2 * 128 * ROWB + 128 * ROWB);   // 165888

    cudaFuncSetAttribute(moe_hmma<1, D_DIM, H_DIM, 256>,
                         cudaFuncAttributeMaxDynamicSharedMemorySize, SMEM1);
    cudaFuncSetAttribute(moe_hmma<2, H_DIM, D_DIM, 128>,
                         cudaFuncAttributeMaxDynamicSharedMemorySize, SMEM2);

    __half *xh, *xl, *hh, *hl, *B1h, *B2h;
    cudaGetSymbolAddress((void**)&xh,  g_xh);  cudaGetSymbolAddress((void**)&xl,  g_xl);
    cudaGetSymbolAddress((void**)&hh,  g_hh);  cudaGetSymbolAddress((void**)&hl,  g_hl);
    cudaGetSymbolAddress((void**)&B1h, g_B1h); cudaGetSymbolAddress((void**)&B2h, g_B2h);

    zero_cnt_kernel<<<1, 32>>>();
    cvt_x_kernel<<<1024, 256>>>(x);
    {   // W1: K=1024, N=4096 -> [E][4096][1024]
        dim3 g(D_DIM / 32, H_DIM / 32, E_NUM);
        pack_w_kernel<<<g, 256>>>(W1, B1h, D_DIM, H_DIM);
    }
    {   // W2: K=4096, N=1024 -> [E][1024][4096]
        dim3 g(H_DIM / 32, D_DIM / 32, E_NUM);
        pack_w_kernel<<<g, 256>>>(W2, B2h, H_DIM, D_DIM);
    }
    router_kernel<<<(N_TOK * 32 + 255) / 256, 256>>>(x, Wr, br);
    offsets_kernel<<<1, 32>>>();

    {   // GEMM1: gathered x [Ne,1024] @ W1^T-packed -> relu -> h (hi/lo fp16)
        dim3 g(CAP / TM, H_DIM / 256, E_NUM);
        moe_hmma<1, D_DIM, H_DIM, 256><<<g, 256, SMEM1>>>(xh, xl, B1h, b1);
    }
    {   // GEMM2: h [Ne,4096] @ W2^T-packed -> y (+b2), TN=128 for more waves
        dim3 g(CAP / TM, D_DIM / 128, E_NUM);
        moe_hmma<2, H_DIM, D_DIM, 128><<<g, 256, SMEM2>>>(hh, hl, B2h, b2);
    }
    combine_kernel<<<N_TOK, 256>>>(out);
}

// round 9
// speedup vs baseline: 1.2762x; 1.2762x over previous
#include <cuda_runtime.h>
#include <cuda_fp16.h>
#include <math.h>
#include <stdint.h>

#define N_TOK 8192
#define D_DIM 1024
#define E_NUM 8
#define H_DIM 4096
#define CAP   8192
#define PAIRS 16384

#define TK 32            // fp16 elems per k-chunk (64 bytes per row)
#define ROWB 80          // padded SMEM row bytes (64 data + 16 pad)
#define NSTAGE 3

// ---------------- device scratch ----------------
__device__ int   g_cnt[E_NUM];
__device__ int   g_off[E_NUM];
__device__ int   g_tok[E_NUM * CAP];
__device__ int   g_tslot[2 * N_TOK];
__device__ float g_tw  [2 * N_TOK];

__device__ __half g_xh[(size_t)N_TOK * D_DIM];
__device__ __half g_xl[(size_t)N_TOK * D_DIM];
__device__ __half g_hh[(size_t)PAIRS * H_DIM];
__device__ __half g_hl[(size_t)PAIRS * H_DIM];
__device__ float  g_y [(size_t)PAIRS * D_DIM];
__device__ __half g_B1h[(size_t)E_NUM * H_DIM * D_DIM];
__device__ __half g_B2h[(size_t)E_NUM * D_DIM * H_DIM];

// ---------------- helpers ----------------
__device__ __forceinline__ uint32_t smem_u32(const void* p) {
    return (uint32_t)__cvta_generic_to_shared(p);
}
#define CP16(dst, src) \
    asm volatile("cp.async.cg.shared.global [%0], [%1], 16;" :: "r"(dst), "l"(src) : "memory")
#define CP_COMMIT() asm volatile("cp.async.commit_group;" ::: "memory")

__device__ __forceinline__ void ldsm4(uint32_t* r, uint32_t addr) {
    asm volatile("ldmatrix.sync.aligned.m8n8.x4.shared.b16 {%0,%1,%2,%3}, [%4];"
        : "=r"(r[0]), "=r"(r[1]), "=r"(r[2]), "=r"(r[3]) : "r"(addr));
}
__device__ __forceinline__ void mma_f16(float* c, const uint32_t* a, const uint32_t* b) {
    asm volatile("mma.sync.aligned.m16n8k16.row.col.f32.f16.f16.f32 "
        "{%0,%1,%2,%3}, {%4,%5,%6,%7}, {%8,%9}, {%0,%1,%2,%3};"
        : "+f"(c[0]), "+f"(c[1]), "+f"(c[2]), "+f"(c[3])
        : "r"(a[0]), "r"(a[1]), "r"(a[2]), "r"(a[3]), "r"(b[0]), "r"(b[1]));
}

// ---------------- small kernels ----------------
__global__ void zero_cnt_kernel() {
    if (threadIdx.x < E_NUM) g_cnt[threadIdx.x] = 0;
}

__global__ void cvt_x_kernel(const float* __restrict__ x) {
    size_t stride = (size_t)gridDim.x * blockDim.x;
    size_t n = (size_t)N_TOK * D_DIM;
    for (size_t i = (size_t)blockIdx.x * blockDim.x + threadIdx.x; i < n; i += stride) {
        float v = x[i];
        __half h = __float2half_rn(v);
        g_xh[i] = h;
        g_xl[i] = __float2half_rn(v - __half2float(h));
    }
}

// W[e][K][N] fp32 -> P[e][N][K] fp16 hi (32x32 tile transpose)
__global__ __launch_bounds__(256)
void pack_w_kernel(const float* __restrict__ W, __half* __restrict__ Ph, int K, int N) {
    __shared__ float s[32][33];
    const int k0 = blockIdx.x * 32, n0 = blockIdx.y * 32, e = blockIdx.z;
    const int tid = threadIdx.x;
    const int kk = tid >> 5, nn = tid & 31;
#pragma unroll
    for (int i = 0; i < 4; i++)
        s[kk + i * 8][nn] = W[((size_t)e * K + k0 + kk + i * 8) * N + n0 + nn];
    __syncthreads();
    const int n_r = tid >> 4;
    const int kp  = (tid & 15) * 2;
#pragma unroll
    for (int i = 0; i < 2; i++) {
        int nr = n_r + i * 16;
        __half2 hp;
        hp.x = __float2half_rn(s[kp][nr]);
        hp.y = __float2half_rn(s[kp + 1][nr]);
        size_t o = ((size_t)e * N + n0 + nr) * K + k0 + kp;
        *(__half2*)(Ph + o) = hp;
    }
}

__global__ void router_kernel(const float* __restrict__ x,
                              const float* __restrict__ Wr,
                              const float* __restrict__ br) {
    int warp = (blockIdx.x * blockDim.x + threadIdx.x) >> 5;
    int lane = threadIdx.x & 31;
    if (warp >= N_TOK) return;
    const float* xr = x + (size_t)warp * D_DIM;
    float acc[8];
#pragma unroll
    for (int e = 0; e < 8; e++) acc[e] = 0.0f;
    for (int d = lane; d < D_DIM; d += 32) {
        float xv = xr[d];
        const float4* w4 = (const float4*)(Wr + (size_t)d * E_NUM);
        float4 a = w4[0], b = w4[1];
        acc[0] += xv * a.x; acc[1] += xv * a.y; acc[2] += xv * a.z; acc[3] += xv * a.w;
        acc[4] += xv * b.x; acc[5] += xv * b.y; acc[6] += xv * b.z; acc[7] += xv * b.w;
    }
#pragma unroll
    for (int off = 16; off > 0; off >>= 1)
#pragma unroll
        for (int e = 0; e < 8; e++)
            acc[e] += __shfl_down_sync(0xffffffffu, acc[e], off);
    if (lane == 0) {
        float lg[8];
#pragma unroll
        for (int e = 0; e < 8; e++) lg[e] = acc[e] + br[e];
        int e0 = 0;
#pragma unroll
        for (int e = 1; e < 8; e++) if (lg[e] > lg[e0]) e0 = e;
        int e1 = (e0 == 0) ? 1 : 0;
#pragma unroll
        for (int e = 0; e < 8; e++)
            if (e != e0 && e != e1 && lg[e] > lg[e1]) e1 = e;
        float z  = __expf(lg[e1] - lg[e0]);
        float w0 = 1.0f / (1.0f + z);
        float w1 = z * w0;
        int p0 = atomicAdd(&g_cnt[e0], 1);
        g_tok[e0 * CAP + p0] = warp;
        int p1 = atomicAdd(&g_cnt[e1], 1);
        g_tok[e1 * CAP + p1] = warp;
        g_tslot[2 * warp]     = e0 * CAP + p0;  g_tw[2 * warp]     = w0;
        g_tslot[2 * warp + 1] = e1 * CAP + p1;  g_tw[2 * warp + 1] = w1;
    }
}

__global__ void offsets_kernel() {
    if (threadIdx.x == 0 && blockIdx.x == 0) {
        int acc = 0;
#pragma unroll
        for (int e = 0; e < E_NUM; e++) { g_off[e] = acc; acc += g_cnt[e]; }
    }
}

__global__ void combine_kernel(float* __restrict__ out) {
    int i = blockIdx.x * blockDim.x + threadIdx.x;
    int t = i >> 8;
    int j = (i & 255) << 2;
    int s0e = g_tslot[2 * t], s1e = g_tslot[2 * t + 1];
    float w0 = g_tw[2 * t], w1 = g_tw[2 * t + 1];
    size_t s0 = (size_t)g_off[s0e >> 13] + (s0e & (CAP - 1));
    size_t s1 = (size_t)g_off[s1e >> 13] + (s1e & (CAP - 1));
    float4 a = *(const float4*)(g_y + s0 * D_DIM + j);
    float4 b = *(const float4*)(g_y + s1 * D_DIM + j);
    float4 o;
    o.x = w0 * a.x + w1 * b.x;
    o.y = w0 * a.y + w1 * b.y;
    o.z = w0 * a.z + w1 * b.z;
    o.w = w0 * a.w + w1 * b.w;
    *(float4*)(out + (size_t)t * D_DIM + j) = o;
}

// ---- grouped GEMM: mma.sync fp16 2-term split, TMV x 256 tile, TK=32 ----
// TMV = 128 (GEMM1, identical to the verified R7 config) or 64 (GEMM2, more waves)
template <int PHASE, int KDIM, int NDIM, int TMV>
__global__ __launch_bounds__(256)
void moe_hmma(const __half* __restrict__ Ahg, const __half* __restrict__ Alg,
              const __half* __restrict__ Bhg,
              const float* __restrict__ bias) {
    constexpr int C   = KDIM / TK;
    constexpr int WM  = TMV / 2;       // warp M tile (64 or 32)
    constexpr int MT  = WM / 16;       // mma m-steps per warp (4 or 2)
    constexpr int AHo = 0;
    constexpr int ALo = TMV * ROWB;
    constexpr int BHo = 2 * TMV * ROWB;
    constexpr uint32_t STGv = (uint32_t)(2 * TMV + 256) * ROWB;

    const int e  = blockIdx.z;
    const int Ne = g_cnt[e];
    const int m0 = blockIdx.x * TMV;
    if (m0 >= Ne) return;
    const int n0 = blockIdx.y * 256;
    const int base = g_off[e];

    extern __shared__ __align__(128) char smem[];
    const uint32_t sb = smem_u32(smem);
    const int tid = threadIdx.x;

    // ---- A loads: thread -> row group (tid>>2), 16B seg (tid&3) ----
    const int r0 = tid >> 2;            // 0..63
    const int sg = (tid & 3) * 16;
    const char *ahp[TMV / 64], *alp[TMV / 64];
#pragma unroll
    for (int j = 0; j < TMV / 64; j++) {
        int rr = min(m0 + r0 + j * 64, Ne - 1);
        size_t i0 = (PHASE == 1) ? (size_t)g_tok[e * CAP + rr] : (size_t)(base + rr);
        ahp[j] = (const char*)(Ahg + i0 * KDIM) + sg;
        alp[j] = (const char*)(Alg + i0 * KDIM) + sg;
    }
    // B: 256 rows, 4 row-groups per thread (hi only)
    const size_t brow = (size_t)e * NDIM + n0 + r0;
    const char* bh0 = (const char*)(Bhg + brow * KDIM) + sg;
    const uint32_t d0 = (uint32_t)r0 * ROWB + sg;

    auto issue = [&](int c) {
        if (c < C) {
            uint32_t st = sb + (uint32_t)(c % NSTAGE) * STGv;
            int cb = c * 64;   // bytes per chunk along K
#pragma unroll
            for (int j = 0; j < TMV / 64; j++) {
                CP16(st + AHo + d0 + j * 64 * ROWB, ahp[j] + cb);
                CP16(st + ALo + d0 + j * 64 * ROWB, alp[j] + cb);
            }
#pragma unroll
            for (int j = 0; j < 4; j++)
                CP16(st + BHo + d0 + j * 64 * ROWB, bh0 + (size_t)j * 64 * KDIM * 2 + cb);
        }
        CP_COMMIT();
    };

    float acc[MT][8][4];
#pragma unroll
    for (int i = 0; i < MT; i++)
#pragma unroll
        for (int j = 0; j < 8; j++)
#pragma unroll
            for (int k = 0; k < 4; k++) acc[i][j][k] = 0.0f;

    const int lane = tid & 31, wid = tid >> 5;
    const int wm = (wid & 1) * WM;        // warp M offset
    const int wn = (wid >> 1) * 64;       // warp N offset
    const uint32_t a_off = (uint32_t)(wm + (lane & 15)) * ROWB + (lane >> 4) * 16;
    const uint32_t b_off = (uint32_t)(wn + (lane & 7) + ((lane >> 4) & 1) * 8) * ROWB
                         + ((lane >> 3) & 1) * 16;

    issue(0);
    issue(1);

    for (int c = 0; c < C; c++) {
        asm volatile("cp.async.wait_group 1;" ::: "memory");
        __syncthreads();
        issue(c + 2);

        const uint32_t st = sb + (uint32_t)(c % NSTAGE) * STGv;
#pragma unroll
        for (int kk = 0; kk < 2; kk++) {
            uint32_t af[4 * MT], tf[16];
            // B hi fragments (shared by both terms)
#pragma unroll
            for (int tn2 = 0; tn2 < 4; tn2++)
                ldsm4(tf + tn2 * 4, st + BHo + b_off + tn2 * 16 * ROWB + kk * 32);
            // A hi x B hi
#pragma unroll
            for (int tm = 0; tm < MT; tm++)
                ldsm4(af + tm * 4, st + AHo + a_off + tm * 16 * ROWB + kk * 32);
#pragma unroll
            for (int tm = 0; tm < MT; tm++)
#pragma unroll
                for (int tn = 0; tn < 8; tn++)
                    mma_f16(acc[tm][tn], af + tm * 4, tf + tn * 2);
            // A lo x B hi (reuse af)
#pragma unroll
            for (int tm = 0; tm < MT; tm++)
                ldsm4(af + tm * 4, st + ALo + a_off + tm * 16 * ROWB + kk * 32);
#pragma unroll
            for (int tm = 0; tm < MT; tm++)
#pragma unroll
                for (int tn = 0; tn < 8; tn++)
                    mma_f16(acc[tm][tn], af + tm * 4, tf + tn * 2);
        }
    }

    // ---- epilogue ----
    const int lr_base  = wm + (lane >> 2);
    const int col_base = n0 + wn + 2 * (lane & 3);
    const float* bp = bias + (size_t)e * NDIM;
#pragma unroll
    for (int tm = 0; tm < MT; tm++) {
#pragma unroll
        for (int half = 0; half < 2; half++) {
            int gr = m0 + lr_base + tm * 16 + half * 8;
            if (gr < Ne) {
                size_t pr = (size_t)(base + gr);
#pragma unroll
                for (int tn = 0; tn < 8; tn++) {
                    int col = col_base + tn * 8;
                    float c0 = acc[tm][tn][half * 2 + 0] + __ldg(bp + col);
                    float c1 = acc[tm][tn][half * 2 + 1] + __ldg(bp + col + 1);
                    if (PHASE == 1) {
                        c0 = fmaxf(c0, 0.f);
                        c1 = fmaxf(c1, 0.f);
                        __half h0 = __float2half_rn(c0);
                        __half h1 = __float2half_rn(c1);
                        __half2 hp; hp.x = h0; hp.y = h1;
                        __half2 lp;
                        lp.x = __float2half_rn(c0 - __half2float(h0));
                        lp.y = __float2half_rn(c1 - __half2float(h1));
                        *(__half2*)(g_hh + pr * H_DIM + col) = hp;
                        *(__half2*)(g_hl + pr * H_DIM + col) = lp;
                    } else {
                        float2 o; o.x = c0; o.y = c1;
                        *(float2*)(g_y + pr * D_DIM + col) = o;
                    }
                }
            }
        }
    }
}

// ---------------- launch ----------------
extern "C" void kernel_launch(void* const* d_in, const int* in_sizes, int n_in,
                              void* d_out, int out_size) {
    const float* x  = (const float*)d_in[0];
    const float* Wr = (const float*)d_in[1];
    const float* br = (const float*)d_in[2];
    const float* W1 = (const float*)d_in[3];
    const float* b1 = (const float*)d_in[4];
    const float* W2 = (const float*)d_in[5];
    const float* b2 = (const float*)d_in[6];
    float* out = (float*)d_out;

    const int SMEM1 = NSTAGE * (2 * 128 + 256) * ROWB;   // 122880
    const int SMEM2 = NSTAGE * (2 * 64 + 256) * ROWB;    // 92160 (2 CTA/SM)

    cudaFuncSetAttribute(moe_hmma<1, D_DIM, H_DIM, 128>,
                         cudaFuncAttributeMaxDynamicSharedMemorySize, SMEM1);
    cudaFuncSetAttribute(moe_hmma<2, H_DIM, D_DIM, 64>,
                         cudaFuncAttributeMaxDynamicSharedMemorySize, SMEM2);

    __half *xh, *xl, *hh, *hl, *B1h, *B2h;
    cudaGetSymbolAddress((void**)&xh,  g_xh);  cudaGetSymbolAddress((void**)&xl,  g_xl);
    cudaGetSymbolAddress((void**)&hh,  g_hh);  cudaGetSymbolAddress((void**)&hl,  g_hl);
    cudaGetSymbolAddress((void**)&B1h, g_B1h); cudaGetSymbolAddress((void**)&B2h, g_B2h);

    zero_cnt_kernel<<<1, 32>>>();
    cvt_x_kernel<<<1024, 256>>>(x);
    {   // W1: K=1024, N=4096 -> [E][4096][1024]
        dim3 g(D_DIM / 32, H_DIM / 32, E_NUM);
        pack_w_kernel<<<g, 256>>>(W1, B1h, D_DIM, H_DIM);
    }
    {   // W2: K=4096, N=1024 -> [E][1024][4096]
        dim3 g(H_DIM / 32, D_DIM / 32, E_NUM);
        pack_w_kernel<<<g, 256>>>(W2, B2h, H_DIM, D_DIM);
    }
    router_kernel<<<(N_TOK * 32 + 255) / 256, 256>>>(x, Wr, br);
    offsets_kernel<<<1, 32>>>();

    {   // GEMM1: gathered x [Ne,1024] @ W1^T-packed -> relu -> h (hi/lo fp16)
        dim3 g(CAP / 128, H_DIM / 256, E_NUM);
        moe_hmma<1, D_DIM, H_DIM, 128><<<g, 256, SMEM1>>>(xh, xl, B1h, b1);
    }
    {   // GEMM2: h [Ne,4096] @ W2^T-packed -> y (+b2); TM=64 for 2x waves + 2 CTA/SM
        dim3 g(CAP / 64, D_DIM / 256, E_NUM);
        moe_hmma<2, H_DIM, D_DIM, 64><<<g, 256, SMEM2>>>(hh, hl, B2h, b2);
    }
    combine_kernel<<<N_TOK, 256>>>(out);
}

// round 10
// speedup vs baseline: 1.3378x; 1.0483x over previous
#include <cuda_runtime.h>
#include <cuda_fp16.h>
#include <math.h>
#include <stdint.h>

#define N_TOK 8192
#define D_DIM 1024
#define E_NUM 8
#define H_DIM 4096
#define CAP   8192
#define PAIRS 16384

#define TK 32            // fp16 elems per k-chunk (64 bytes per row)
#define ROWB 80          // padded SMEM row bytes (64 data + 16 pad)
#define NSTAGE 3

// ---------------- device scratch ----------------
__device__ int   g_cnt[E_NUM];
__device__ int   g_off[E_NUM];
__device__ int   g_tok[E_NUM * CAP];
__device__ int   g_tslot[2 * N_TOK];
__device__ float g_tw  [2 * N_TOK];

__device__ __half g_xh[(size_t)N_TOK * D_DIM];
__device__ __half g_xl[(size_t)N_TOK * D_DIM];
__device__ __half g_hh[(size_t)PAIRS * H_DIM];
__device__ __half g_hl[(size_t)PAIRS * H_DIM];
__device__ float  g_y [(size_t)PAIRS * D_DIM];
__device__ __half g_B1h[(size_t)E_NUM * H_DIM * D_DIM];
__device__ __half g_B2h[(size_t)E_NUM * D_DIM * H_DIM];

// ---------------- helpers ----------------
__device__ __forceinline__ uint32_t smem_u32(const void* p) {
    return (uint32_t)__cvta_generic_to_shared(p);
}
#define CP16(dst, src) \
    asm volatile("cp.async.cg.shared.global [%0], [%1], 16;" :: "r"(dst), "l"(src) : "memory")
#define CP_COMMIT() asm volatile("cp.async.commit_group;" ::: "memory")

__device__ __forceinline__ void ldsm4(uint32_t* r, uint32_t addr) {
    asm volatile("ldmatrix.sync.aligned.m8n8.x4.shared.b16 {%0,%1,%2,%3}, [%4];"
        : "=r"(r[0]), "=r"(r[1]), "=r"(r[2]), "=r"(r[3]) : "r"(addr));
}
__device__ __forceinline__ void mma_f16(float* c, const uint32_t* a, const uint32_t* b) {
    asm volatile("mma.sync.aligned.m16n8k16.row.col.f32.f16.f16.f32 "
        "{%0,%1,%2,%3}, {%4,%5,%6,%7}, {%8,%9}, {%0,%1,%2,%3};"
        : "+f"(c[0]), "+f"(c[1]), "+f"(c[2]), "+f"(c[3])
        : "r"(a[0]), "r"(a[1]), "r"(a[2]), "r"(a[3]), "r"(b[0]), "r"(b[1]));
}

// ---------------- small kernels ----------------
__global__ void zero_cnt_kernel() {
    if (threadIdx.x < E_NUM) g_cnt[threadIdx.x] = 0;
}

__global__ void cvt_x_kernel(const float* __restrict__ x) {
    size_t stride = (size_t)gridDim.x * blockDim.x;
    size_t n = (size_t)N_TOK * D_DIM;
    for (size_t i = (size_t)blockIdx.x * blockDim.x + threadIdx.x; i < n; i += stride) {
        float v = x[i];
        __half h = __float2half_rn(v);
        g_xh[i] = h;
        g_xl[i] = __float2half_rn(v - __half2float(h));
    }
}

// W[e][K][N] fp32 -> P[e][N][K] fp16 hi (32x32 tile transpose)
__global__ __launch_bounds__(256)
void pack_w_kernel(const float* __restrict__ W, __half* __restrict__ Ph, int K, int N) {
    __shared__ float s[32][33];
    const int k0 = blockIdx.x * 32, n0 = blockIdx.y * 32, e = blockIdx.z;
    const int tid = threadIdx.x;
    const int kk = tid >> 5, nn = tid & 31;
#pragma unroll
    for (int i = 0; i < 4; i++)
        s[kk + i * 8][nn] = W[((size_t)e * K + k0 + kk + i * 8) * N + n0 + nn];
    __syncthreads();
    const int n_r = tid >> 4;
    const int kp  = (tid & 15) * 2;
#pragma unroll
    for (int i = 0; i < 2; i++) {
        int nr = n_r + i * 16;
        __half2 hp;
        hp.x = __float2half_rn(s[kp][nr]);
        hp.y = __float2half_rn(s[kp + 1][nr]);
        size_t o = ((size_t)e * N + n0 + nr) * K + k0 + kp;
        *(__half2*)(Ph + o) = hp;
    }
}

__global__ void router_kernel(const float* __restrict__ x,
                              const float* __restrict__ Wr,
                              const float* __restrict__ br) {
    int warp = (blockIdx.x * blockDim.x + threadIdx.x) >> 5;
    int lane = threadIdx.x & 31;
    if (warp >= N_TOK) return;
    const float* xr = x + (size_t)warp * D_DIM;
    float acc[8];
#pragma unroll
    for (int e = 0; e < 8; e++) acc[e] = 0.0f;
    for (int d = lane; d < D_DIM; d += 32) {
        float xv = xr[d];
        const float4* w4 = (const float4*)(Wr + (size_t)d * E_NUM);
        float4 a = w4[0], b = w4[1];
        acc[0] += xv * a.x; acc[1] += xv * a.y; acc[2] += xv * a.z; acc[3] += xv * a.w;
        acc[4] += xv * b.x; acc[5] += xv * b.y; acc[6] += xv * b.z; acc[7] += xv * b.w;
    }
#pragma unroll
    for (int off = 16; off > 0; off >>= 1)
#pragma unroll
        for (int e = 0; e < 8; e++)
            acc[e] += __shfl_down_sync(0xffffffffu, acc[e], off);
    if (lane == 0) {
        float lg[8];
#pragma unroll
        for (int e = 0; e < 8; e++) lg[e] = acc[e] + br[e];
        int e0 = 0;
#pragma unroll
        for (int e = 1; e < 8; e++) if (lg[e] > lg[e0]) e0 = e;
        int e1 = (e0 == 0) ? 1 : 0;
#pragma unroll
        for (int e = 0; e < 8; e++)
            if (e != e0 && e != e1 && lg[e] > lg[e1]) e1 = e;
        float z  = __expf(lg[e1] - lg[e0]);
        float w0 = 1.0f / (1.0f + z);
        float w1 = z * w0;
        int p0 = atomicAdd(&g_cnt[e0], 1);
        g_tok[e0 * CAP + p0] = warp;
        int p1 = atomicAdd(&g_cnt[e1], 1);
        g_tok[e1 * CAP + p1] = warp;
        g_tslot[2 * warp]     = e0 * CAP + p0;  g_tw[2 * warp]     = w0;
        g_tslot[2 * warp + 1] = e1 * CAP + p1;  g_tw[2 * warp + 1] = w1;
    }
}

__global__ void offsets_kernel() {
    if (threadIdx.x == 0 && blockIdx.x == 0) {
        int acc = 0;
#pragma unroll
        for (int e = 0; e < E_NUM; e++) { g_off[e] = acc; acc += g_cnt[e]; }
    }
}

__global__ void combine_kernel(float* __restrict__ out) {
    int i = blockIdx.x * blockDim.x + threadIdx.x;
    int t = i >> 8;
    int j = (i & 255) << 2;
    int s0e = g_tslot[2 * t], s1e = g_tslot[2 * t + 1];
    float w0 = g_tw[2 * t], w1 = g_tw[2 * t + 1];
    size_t s0 = (size_t)g_off[s0e >> 13] + (s0e & (CAP - 1));
    size_t s1 = (size_t)g_off[s1e >> 13] + (s1e & (CAP - 1));
    float4 a = *(const float4*)(g_y + s0 * D_DIM + j);
    float4 b = *(const float4*)(g_y + s1 * D_DIM + j);
    float4 o;
    o.x = w0 * a.x + w1 * b.x;
    o.y = w0 * a.y + w1 * b.y;
    o.z = w0 * a.z + w1 * b.z;
    o.w = w0 * a.w + w1 * b.w;
    *(float4*)(out + (size_t)t * D_DIM + j) = o;
}

// ---- grouped GEMM: mma.sync fp16 2-term split, TMV x 256 tile, TK=32 ----
// TMV=64: 92 KB smem -> 2 CTAs/SM co-resident
template <int PHASE, int KDIM, int NDIM, int TMV>
__global__ __launch_bounds__(256)
void moe_hmma(const __half* __restrict__ Ahg, const __half* __restrict__ Alg,
              const __half* __restrict__ Bhg,
              const float* __restrict__ bias) {
    constexpr int C   = KDIM / TK;
    constexpr int WM  = TMV / 2;       // warp M tile (64 or 32)
    constexpr int MT  = WM / 16;       // mma m-steps per warp (4 or 2)
    constexpr int AHo = 0;
    constexpr int ALo = TMV * ROWB;
    constexpr int BHo = 2 * TMV * ROWB;
    constexpr uint32_t STGv = (uint32_t)(2 * TMV + 256) * ROWB;

    const int e  = blockIdx.z;
    const int Ne = g_cnt[e];
    const int m0 = blockIdx.x * TMV;
    if (m0 >= Ne) return;
    const int n0 = blockIdx.y * 256;
    const int base = g_off[e];

    extern __shared__ __align__(128) char smem[];
    const uint32_t sb = smem_u32(smem);
    const int tid = threadIdx.x;

    // ---- A loads: thread -> row group (tid>>2), 16B seg (tid&3) ----
    const int r0 = tid >> 2;            // 0..63
    const int sg = (tid & 3) * 16;
    const char *ahp[TMV / 64], *alp[TMV / 64];
#pragma unroll
    for (int j = 0; j < TMV / 64; j++) {
        int rr = min(m0 + r0 + j * 64, Ne - 1);
        size_t i0 = (PHASE == 1) ? (size_t)g_tok[e * CAP + rr] : (size_t)(base + rr);
        ahp[j] = (const char*)(Ahg + i0 * KDIM) + sg;
        alp[j] = (const char*)(Alg + i0 * KDIM) + sg;
    }
    // B: 256 rows, 4 row-groups per thread (hi only)
    const size_t brow = (size_t)e * NDIM + n0 + r0;
    const char* bh0 = (const char*)(Bhg + brow * KDIM) + sg;
    const uint32_t d0 = (uint32_t)r0 * ROWB + sg;

    auto issue = [&](int c) {
        if (c < C) {
            uint32_t st = sb + (uint32_t)(c % NSTAGE) * STGv;
            int cb = c * 64;   // bytes per chunk along K
#pragma unroll
            for (int j = 0; j < TMV / 64; j++) {
                CP16(st + AHo + d0 + j * 64 * ROWB, ahp[j] + cb);
                CP16(st + ALo + d0 + j * 64 * ROWB, alp[j] + cb);
            }
#pragma unroll
            for (int j = 0; j < 4; j++)
                CP16(st + BHo + d0 + j * 64 * ROWB, bh0 + (size_t)j * 64 * KDIM * 2 + cb);
        }
        CP_COMMIT();
    };

    float acc[MT][8][4];
#pragma unroll
    for (int i = 0; i < MT; i++)
#pragma unroll
        for (int j = 0; j < 8; j++)
#pragma unroll
            for (int k = 0; k < 4; k++) acc[i][j][k] = 0.0f;

    const int lane = tid & 31, wid = tid >> 5;
    const int wm = (wid & 1) * WM;        // warp M offset
    const int wn = (wid >> 1) * 64;       // warp N offset
    const uint32_t a_off = (uint32_t)(wm + (lane & 15)) * ROWB + (lane >> 4) * 16;
    const uint32_t b_off = (uint32_t)(wn + (lane & 7) + ((lane >> 4) & 1) * 8) * ROWB
                         + ((lane >> 3) & 1) * 16;

    issue(0);
    issue(1);

    for (int c = 0; c < C; c++) {
        asm volatile("cp.async.wait_group 1;" ::: "memory");
        __syncthreads();
        issue(c + 2);

        const uint32_t st = sb + (uint32_t)(c % NSTAGE) * STGv;
#pragma unroll
        for (int kk = 0; kk < 2; kk++) {
            uint32_t af[4 * MT], tf[16];
            // B hi fragments (shared by both terms)
#pragma unroll
            for (int tn2 = 0; tn2 < 4; tn2++)
                ldsm4(tf + tn2 * 4, st + BHo + b_off + tn2 * 16 * ROWB + kk * 32);
            // A hi x B hi
#pragma unroll
            for (int tm = 0; tm < MT; tm++)
                ldsm4(af + tm * 4, st + AHo + a_off + tm * 16 * ROWB + kk * 32);
#pragma unroll
            for (int tm = 0; tm < MT; tm++)
#pragma unroll
                for (int tn = 0; tn < 8; tn++)
                    mma_f16(acc[tm][tn], af + tm * 4, tf + tn * 2);
            // A lo x B hi (reuse af)
#pragma unroll
            for (int tm = 0; tm < MT; tm++)
                ldsm4(af + tm * 4, st + ALo + a_off + tm * 16 * ROWB + kk * 32);
#pragma unroll
            for (int tm = 0; tm < MT; tm++)
#pragma unroll
                for (int tn = 0; tn < 8; tn++)
                    mma_f16(acc[tm][tn], af + tm * 4, tf + tn * 2);
        }
    }

    // ---- epilogue ----
    const int lr_base  = wm + (lane >> 2);
    const int col_base = n0 + wn + 2 * (lane & 3);
    const float* bp = bias + (size_t)e * NDIM;
#pragma unroll
    for (int tm = 0; tm < MT; tm++) {
#pragma unroll
        for (int half = 0; half < 2; half++) {
            int gr = m0 + lr_base + tm * 16 + half * 8;
            if (gr < Ne) {
                size_t pr = (size_t)(base + gr);
#pragma unroll
                for (int tn = 0; tn < 8; tn++) {
                    int col = col_base + tn * 8;
                    float c0 = acc[tm][tn][half * 2 + 0] + __ldg(bp + col);
                    float c1 = acc[tm][tn][half * 2 + 1] + __ldg(bp + col + 1);
                    if (PHASE == 1) {
                        c0 = fmaxf(c0, 0.f);
                        c1 = fmaxf(c1, 0.f);
                        __half h0 = __float2half_rn(c0);
                        __half h1 = __float2half_rn(c1);
                        __half2 hp; hp.x = h0; hp.y = h1;
                        __half2 lp;
                        lp.x = __float2half_rn(c0 - __half2float(h0));
                        lp.y = __float2half_rn(c1 - __half2float(h1));
                        *(__half2*)(g_hh + pr * H_DIM + col) = hp;
                        *(__half2*)(g_hl + pr * H_DIM + col) = lp;
                    } else {
                        float2 o; o.x = c0; o.y = c1;
                        *(float2*)(g_y + pr * D_DIM + col) = o;
                    }
                }
            }
        }
    }
}

// ---------------- launch ----------------
extern "C" void kernel_launch(void* const* d_in, const int* in_sizes, int n_in,
                              void* d_out, int out_size) {
    const float* x  = (const float*)d_in[0];
    const float* Wr = (const float*)d_in[1];
    const float* br = (const float*)d_in[2];
    const float* W1 = (const float*)d_in[3];
    const float* b1 = (const float*)d_in[4];
    const float* W2 = (const float*)d_in[5];
    const float* b2 = (const float*)d_in[6];
    float* out = (float*)d_out;

    const int SMEM64 = NSTAGE * (2 * 64 + 256) * ROWB;    // 92160 -> 2 CTA/SM

    cudaFuncSetAttribute(moe_hmma<1, D_DIM, H_DIM, 64>,
                         cudaFuncAttributeMaxDynamicSharedMemorySize, SMEM64);
    cudaFuncSetAttribute(moe_hmma<2, H_DIM, D_DIM, 64>,
                         cudaFuncAttributeMaxDynamicSharedMemorySize, SMEM64);

    __half *xh, *xl, *hh, *hl, *B1h, *B2h;
    cudaGetSymbolAddress((void**)&xh,  g_xh);  cudaGetSymbolAddress((void**)&xl,  g_xl);
    cudaGetSymbolAddress((void**)&hh,  g_hh);  cudaGetSymbolAddress((void**)&hl,  g_hl);
    cudaGetSymbolAddress((void**)&B1h, g_B1h); cudaGetSymbolAddress((void**)&B2h, g_B2h);

    zero_cnt_kernel<<<1, 32>>>();
    cvt_x_kernel<<<1024, 256>>>(x);
    {   // W1: K=1024, N=4096 -> [E][4096][1024]
        dim3 g(D_DIM / 32, H_DIM / 32, E_NUM);
        pack_w_kernel<<<g, 256>>>(W1, B1h, D_DIM, H_DIM);
    }
    {   // W2: K=4096, N=1024 -> [E][1024][4096]
        dim3 g(H_DIM / 32, D_DIM / 32, E_NUM);
        pack_w_kernel<<<g, 256>>>(W2, B2h, H_DIM, D_DIM);
    }
    router_kernel<<<(N_TOK * 32 + 255) / 256, 256>>>(x, Wr, br);
    offsets_kernel<<<1, 32>>>();

    {   // GEMM1: gathered x [Ne,1024] @ W1^T-packed -> relu -> h; TM=64, 2 CTA/SM
        dim3 g(CAP / 64, H_DIM / 256, E_NUM);
        moe_hmma<1, D_DIM, H_DIM, 64><<<g, 256, SMEM64>>>(xh, xl, B1h, b1);
    }
    {   // GEMM2: h [Ne,4096] @ W2^T-packed -> y (+b2); TM=64, 2 CTA/SM
        dim3 g(CAP / 64, D_DIM / 256, E_NUM);
        moe_hmma<2, H_DIM, D_DIM, 64><<<g, 256, SMEM64>>>(hh, hl, B2h, b2);
    }
    combine_kernel<<<N_TOK, 256>>>(out);
}

// round 11
// speedup vs baseline: 1.5744x; 1.1768x over previous
#include <cuda_runtime.h>
#include <cuda_fp16.h>
#include <math.h>
#include <stdint.h>

#define N_TOK 8192
#define D_DIM 1024
#define E_NUM 8
#define H_DIM 4096
#define CAP   8192
#define PAIRS 16384

#define TK 32            // fp16 elems per k-chunk (64 bytes per row)
#define ROWB 80          // padded SMEM row bytes (64 data + 16 pad)
#define NSTAGE 3

// ---------------- device scratch ----------------
__device__ int   g_cnt[E_NUM];
__device__ int   g_off[E_NUM];
__device__ int   g_tok[E_NUM * CAP];
__device__ int   g_tslot[2 * N_TOK];
__device__ float g_tw  [2 * N_TOK];

__device__ __half g_xh[(size_t)N_TOK * D_DIM];
__device__ __half g_xl[(size_t)N_TOK * D_DIM];
__device__ __half g_hh[(size_t)PAIRS * H_DIM];
__device__ float  g_y [(size_t)PAIRS * D_DIM];
__device__ __half g_B1h[(size_t)E_NUM * H_DIM * D_DIM];
__device__ __half g_B2h[(size_t)E_NUM * D_DIM * H_DIM];

// ---------------- helpers ----------------
__device__ __forceinline__ uint32_t smem_u32(const void* p) {
    return (uint32_t)__cvta_generic_to_shared(p);
}
#define CP16(dst, src) \
    asm volatile("cp.async.cg.shared.global [%0], [%1], 16;" :: "r"(dst), "l"(src) : "memory")
#define CP_COMMIT() asm volatile("cp.async.commit_group;" ::: "memory")

__device__ __forceinline__ void ldsm4(uint32_t* r, uint32_t addr) {
    asm volatile("ldmatrix.sync.aligned.m8n8.x4.shared.b16 {%0,%1,%2,%3}, [%4];"
        : "=r"(r[0]), "=r"(r[1]), "=r"(r[2]), "=r"(r[3]) : "r"(addr));
}
__device__ __forceinline__ void mma_f16(float* c, const uint32_t* a, const uint32_t* b) {
    asm volatile("mma.sync.aligned.m16n8k16.row.col.f32.f16.f16.f32 "
        "{%0,%1,%2,%3}, {%4,%5,%6,%7}, {%8,%9}, {%0,%1,%2,%3};"
        : "+f"(c[0]), "+f"(c[1]), "+f"(c[2]), "+f"(c[3])
        : "r"(a[0]), "r"(a[1]), "r"(a[2]), "r"(a[3]), "r"(b[0]), "r"(b[1]));
}

// ---------------- small kernels ----------------
__global__ void zero_cnt_kernel() {
    if (threadIdx.x < E_NUM) g_cnt[threadIdx.x] = 0;
}

__global__ void cvt_x_kernel(const float* __restrict__ x) {
    size_t stride = (size_t)gridDim.x * blockDim.x;
    size_t n = (size_t)N_TOK * D_DIM;
    for (size_t i = (size_t)blockIdx.x * blockDim.x + threadIdx.x; i < n; i += stride) {
        float v = x[i];
        __half h = __float2half_rn(v);
        g_xh[i] = h;
        g_xl[i] = __float2half_rn(v - __half2float(h));
    }
}

// W[e][K][N] fp32 -> P[e][N][K] fp16 hi (32x32 tile transpose)
__global__ __launch_bounds__(256)
void pack_w_kernel(const float* __restrict__ W, __half* __restrict__ Ph, int K, int N) {
    __shared__ float s[32][33];
    const int k0 = blockIdx.x * 32, n0 = blockIdx.y * 32, e = blockIdx.z;
    const int tid = threadIdx.x;
    const int kk = tid >> 5, nn = tid & 31;
#pragma unroll
    for (int i = 0; i < 4; i++)
        s[kk + i * 8][nn] = W[((size_t)e * K + k0 + kk + i * 8) * N + n0 + nn];
    __syncthreads();
    const int n_r = tid >> 4;
    const int kp  = (tid & 15) * 2;
#pragma unroll
    for (int i = 0; i < 2; i++) {
        int nr = n_r + i * 16;
        __half2 hp;
        hp.x = __float2half_rn(s[kp][nr]);
        hp.y = __float2half_rn(s[kp + 1][nr]);
        size_t o = ((size_t)e * N + n0 + nr) * K + k0 + kp;
        *(__half2*)(Ph + o) = hp;
    }
}

__global__ void router_kernel(const float* __restrict__ x,
                              const float* __restrict__ Wr,
                              const float* __restrict__ br) {
    int warp = (blockIdx.x * blockDim.x + threadIdx.x) >> 5;
    int lane = threadIdx.x & 31;
    if (warp >= N_TOK) return;
    const float* xr = x + (size_t)warp * D_DIM;
    float acc[8];
#pragma unroll
    for (int e = 0; e < 8; e++) acc[e] = 0.0f;
    for (int d = lane; d < D_DIM; d += 32) {
        float xv = xr[d];
        const float4* w4 = (const float4*)(Wr + (size_t)d * E_NUM);
        float4 a = w4[0], b = w4[1];
        acc[0] += xv * a.x; acc[1] += xv * a.y; acc[2] += xv * a.z; acc[3] += xv * a.w;
        acc[4] += xv * b.x; acc[5] += xv * b.y; acc[6] += xv * b.z; acc[7] += xv * b.w;
    }
#pragma unroll
    for (int off = 16; off > 0; off >>= 1)
#pragma unroll
        for (int e = 0; e < 8; e++)
            acc[e] += __shfl_down_sync(0xffffffffu, acc[e], off);
    if (lane == 0) {
        float lg[8];
#pragma unroll
        for (int e = 0; e < 8; e++) lg[e] = acc[e] + br[e];
        int e0 = 0;
#pragma unroll
        for (int e = 1; e < 8; e++) if (lg[e] > lg[e0]) e0 = e;
        int e1 = (e0 == 0) ? 1 : 0;
#pragma unroll
        for (int e = 0; e < 8; e++)
            if (e != e0 && e != e1 && lg[e] > lg[e1]) e1 = e;
        float z  = __expf(lg[e1] - lg[e0]);
        float w0 = 1.0f / (1.0f + z);
        float w1 = z * w0;
        int p0 = atomicAdd(&g_cnt[e0], 1);
        g_tok[e0 * CAP + p0] = warp;
        int p1 = atomicAdd(&g_cnt[e1], 1);
        g_tok[e1 * CAP + p1] = warp;
        g_tslot[2 * warp]     = e0 * CAP + p0;  g_tw[2 * warp]     = w0;
        g_tslot[2 * warp + 1] = e1 * CAP + p1;  g_tw[2 * warp + 1] = w1;
    }
}

__global__ void offsets_kernel() {
    if (threadIdx.x == 0 && blockIdx.x == 0) {
        int acc = 0;
#pragma unroll
        for (int e = 0; e < E_NUM; e++) { g_off[e] = acc; acc += g_cnt[e]; }
    }
}

__global__ void combine_kernel(float* __restrict__ out) {
    int i = blockIdx.x * blockDim.x + threadIdx.x;
    int t = i >> 8;
    int j = (i & 255) << 2;
    int s0e = g_tslot[2 * t], s1e = g_tslot[2 * t + 1];
    float w0 = g_tw[2 * t], w1 = g_tw[2 * t + 1];
    size_t s0 = (size_t)g_off[s0e >> 13] + (s0e & (CAP - 1));
    size_t s1 = (size_t)g_off[s1e >> 13] + (s1e & (CAP - 1));
    float4 a = *(const float4*)(g_y + s0 * D_DIM + j);
    float4 b = *(const float4*)(g_y + s1 * D_DIM + j);
    float4 o;
    o.x = w0 * a.x + w1 * b.x;
    o.y = w0 * a.y + w1 * b.y;
    o.z = w0 * a.z + w1 * b.z;
    o.w = w0 * a.w + w1 * b.w;
    *(float4*)(out + (size_t)t * D_DIM + j) = o;
}

// ---- grouped GEMM: mma.sync fp16, TERMS-way A split, TMV x 256 tile, TK=32 ----
// TMV=64: 2 CTAs/SM co-resident. TERMS=2 (GEMM1: x hi+lo) or 1 (GEMM2: h fp16 only)
template <int PHASE, int KDIM, int NDIM, int TMV, int TERMS>
__global__ __launch_bounds__(256)
void moe_hmma(const __half* __restrict__ Ahg, const __half* __restrict__ Alg,
              const __half* __restrict__ Bhg,
              const float* __restrict__ bias) {
    constexpr int C   = KDIM / TK;
    constexpr int WM  = TMV / 2;       // warp M tile
    constexpr int MT  = WM / 16;       // mma m-steps per warp
    constexpr int AHo = 0;
    constexpr int ALo = TMV * ROWB;                 // used only if TERMS==2
    constexpr int BHo = TERMS * TMV * ROWB;
    constexpr uint32_t STGv = (uint32_t)(TERMS * TMV + 256) * ROWB;

    const int e  = blockIdx.z;
    const int Ne = g_cnt[e];
    const int m0 = blockIdx.x * TMV;
    if (m0 >= Ne) return;
    const int n0 = blockIdx.y * 256;
    const int base = g_off[e];

    extern __shared__ __align__(128) char smem[];
    const uint32_t sb = smem_u32(smem);
    const int tid = threadIdx.x;

    // ---- A loads: thread -> row group (tid>>2), 16B seg (tid&3) ----
    const int r0 = tid >> 2;            // 0..63
    const int sg = (tid & 3) * 16;
    const char *ahp, *alp;
    {
        int rr = min(m0 + r0, Ne - 1);
        size_t i0 = (PHASE == 1) ? (size_t)g_tok[e * CAP + rr] : (size_t)(base + rr);
        ahp = (const char*)(Ahg + i0 * KDIM) + sg;
        alp = (TERMS == 2) ? (const char*)(Alg + i0 * KDIM) + sg : nullptr;
    }
    // B: 256 rows, 4 row-groups per thread (hi only)
    const size_t brow = (size_t)e * NDIM + n0 + r0;
    const char* bh0 = (const char*)(Bhg + brow * KDIM) + sg;
    const uint32_t d0 = (uint32_t)r0 * ROWB + sg;

    auto issue = [&](int c) {
        if (c < C) {
            uint32_t st = sb + (uint32_t)(c % NSTAGE) * STGv;
            int cb = c * 64;   // bytes per chunk along K
            CP16(st + AHo + d0, ahp + cb);
            if (TERMS == 2) CP16(st + ALo + d0, alp + cb);
#pragma unroll
            for (int j = 0; j < 4; j++)
                CP16(st + BHo + d0 + j * 64 * ROWB, bh0 + (size_t)j * 64 * KDIM * 2 + cb);
        }
        CP_COMMIT();
    };

    float acc[MT][8][4];
#pragma unroll
    for (int i = 0; i < MT; i++)
#pragma unroll
        for (int j = 0; j < 8; j++)
#pragma unroll
            for (int k = 0; k < 4; k++) acc[i][j][k] = 0.0f;

    const int lane = tid & 31, wid = tid >> 5;
    const int wm = (wid & 1) * WM;        // warp M offset
    const int wn = (wid >> 1) * 64;       // warp N offset
    const uint32_t a_off = (uint32_t)(wm + (lane & 15)) * ROWB + (lane >> 4) * 16;
    const uint32_t b_off = (uint32_t)(wn + (lane & 7) + ((lane >> 4) & 1) * 8) * ROWB
                         + ((lane >> 3) & 1) * 16;

    issue(0);
    issue(1);

    for (int c = 0; c < C; c++) {
        asm volatile("cp.async.wait_group 1;" ::: "memory");
        __syncthreads();
        issue(c + 2);

        const uint32_t st = sb + (uint32_t)(c % NSTAGE) * STGv;
#pragma unroll
        for (int kk = 0; kk < 2; kk++) {
            uint32_t af[4 * MT], tf[16];
            // B hi fragments (shared by all terms)
#pragma unroll
            for (int tn2 = 0; tn2 < 4; tn2++)
                ldsm4(tf + tn2 * 4, st + BHo + b_off + tn2 * 16 * ROWB + kk * 32);
            // A hi x B hi
#pragma unroll
            for (int tm = 0; tm < MT; tm++)
                ldsm4(af + tm * 4, st + AHo + a_off + tm * 16 * ROWB + kk * 32);
#pragma unroll
            for (int tm = 0; tm < MT; tm++)
#pragma unroll
                for (int tn = 0; tn < 8; tn++)
                    mma_f16(acc[tm][tn], af + tm * 4, tf + tn * 2);
            if (TERMS == 2) {
                // A lo x B hi (reuse af)
#pragma unroll
                for (int tm = 0; tm < MT; tm++)
                    ldsm4(af + tm * 4, st + ALo + a_off + tm * 16 * ROWB + kk * 32);
#pragma unroll
                for (int tm = 0; tm < MT; tm++)
#pragma unroll
                    for (int tn = 0; tn < 8; tn++)
                        mma_f16(acc[tm][tn], af + tm * 4, tf + tn * 2);
            }
        }
    }

    // ---- epilogue ----
    const int lr_base  = wm + (lane >> 2);
    const int col_base = n0 + wn + 2 * (lane & 3);
    const float* bp = bias + (size_t)e * NDIM;
#pragma unroll
    for (int tm = 0; tm < MT; tm++) {
#pragma unroll
        for (int half = 0; half < 2; half++) {
            int gr = m0 + lr_base + tm * 16 + half * 8;
            if (gr < Ne) {
                size_t pr = (size_t)(base + gr);
#pragma unroll
                for (int tn = 0; tn < 8; tn++) {
                    int col = col_base + tn * 8;
                    float c0 = acc[tm][tn][half * 2 + 0] + __ldg(bp + col);
                    float c1 = acc[tm][tn][half * 2 + 1] + __ldg(bp + col + 1);
                    if (PHASE == 1) {
                        c0 = fmaxf(c0, 0.f);
                        c1 = fmaxf(c1, 0.f);
                        __half2 hp;
                        hp.x = __float2half_rn(c0);
                        hp.y = __float2half_rn(c1);
                        *(__half2*)(g_hh + pr * H_DIM + col) = hp;
                    } else {
                        float2 o; o.x = c0; o.y = c1;
                        *(float2*)(g_y + pr * D_DIM + col) = o;
                    }
                }
            }
        }
    }
}

// ---------------- launch ----------------
extern "C" void kernel_launch(void* const* d_in, const int* in_sizes, int n_in,
                              void* d_out, int out_size) {
    const float* x  = (const float*)d_in[0];
    const float* Wr = (const float*)d_in[1];
    const float* br = (const float*)d_in[2];
    const float* W1 = (const float*)d_in[3];
    const float* b1 = (const float*)d_in[4];
    const float* W2 = (const float*)d_in[5];
    const float* b2 = (const float*)d_in[6];
    float* out = (float*)d_out;

    const int SMEM1 = NSTAGE * (2 * 64 + 256) * ROWB;   // 92160 -> 2 CTA/SM
    const int SMEM2 = NSTAGE * (1 * 64 + 256) * ROWB;   // 76800 -> 2 CTA/SM

    cudaFuncSetAttribute(moe_hmma<1, D_DIM, H_DIM, 64, 2>,
                         cudaFuncAttributeMaxDynamicSharedMemorySize, SMEM1);
    cudaFuncSetAttribute(moe_hmma<2, H_DIM, D_DIM, 64, 1>,
                         cudaFuncAttributeMaxDynamicSharedMemorySize, SMEM2);

    __half *xh, *xl, *hh, *B1h, *B2h;
    cudaGetSymbolAddress((void**)&xh,  g_xh);  cudaGetSymbolAddress((void**)&xl,  g_xl);
    cudaGetSymbolAddress((void**)&hh,  g_hh);
    cudaGetSymbolAddress((void**)&B1h, g_B1h); cudaGetSymbolAddress((void**)&B2h, g_B2h);

    zero_cnt_kernel<<<1, 32>>>();
    cvt_x_kernel<<<1024, 256>>>(x);
    {   // W1: K=1024, N=4096 -> [E][4096][1024]
        dim3 g(D_DIM / 32, H_DIM / 32, E_NUM);
        pack_w_kernel<<<g, 256>>>(W1, B1h, D_DIM, H_DIM);
    }
    {   // W2: K=4096, N=1024 -> [E][1024][4096]
        dim3 g(H_DIM / 32, D_DIM / 32, E_NUM);
        pack_w_kernel<<<g, 256>>>(W2, B2h, H_DIM, D_DIM);
    }
    router_kernel<<<(N_TOK * 32 + 255) / 256, 256>>>(x, Wr, br);
    offsets_kernel<<<1, 32>>>();

    {   // GEMM1: gathered x [Ne,1024] @ W1 -> relu -> h (fp16), 2-term split
        dim3 g(CAP / 64, H_DIM / 256, E_NUM);
        moe_hmma<1, D_DIM, H_DIM, 64, 2><<<g, 256, SMEM1>>>(xh, xl, B1h, b1);
    }
    {   // GEMM2: h [Ne,4096] @ W2 -> y (+b2), single fp16 term
        dim3 g(CAP / 64, D_DIM / 256, E_NUM);
        moe_hmma<2, H_DIM, D_DIM, 64, 1><<<g, 256, SMEM2>>>(hh, nullptr, B2h, b2);
    }
    combine_kernel<<<N_TOK, 256>>>(out);
}

// round 12
// speedup vs baseline: 1.8796x; 1.1939x over previous
#include <cuda_runtime.h>
#include <cuda_fp16.h>
#include <math.h>
#include <stdint.h>

#define N_TOK 8192
#define D_DIM 1024
#define E_NUM 8
#define H_DIM 4096
#define CAP   8192
#define PAIRS 16384

#define TK 32            // fp16 elems per k-chunk (64 bytes per row)
#define ROWB 80          // padded SMEM row bytes (64 data + 16 pad)
#define NSTAGE 3

// ---------------- device scratch ----------------
__device__ int   g_cnt[E_NUM];
__device__ int   g_off[E_NUM];
__device__ int   g_tok[E_NUM * CAP];
__device__ int   g_tslot[2 * N_TOK];
__device__ float g_tw  [2 * N_TOK];

__device__ __half g_xh[(size_t)N_TOK * D_DIM];
__device__ __half g_hh[(size_t)PAIRS * H_DIM];
__device__ float  g_y [(size_t)PAIRS * D_DIM];
__device__ __half g_B1h[(size_t)E_NUM * H_DIM * D_DIM];
__device__ __half g_B2h[(size_t)E_NUM * D_DIM * H_DIM];

// ---------------- helpers ----------------
__device__ __forceinline__ uint32_t smem_u32(const void* p) {
    return (uint32_t)__cvta_generic_to_shared(p);
}
#define CP16(dst, src) \
    asm volatile("cp.async.cg.shared.global [%0], [%1], 16;" :: "r"(dst), "l"(src) : "memory")
#define CP_COMMIT() asm volatile("cp.async.commit_group;" ::: "memory")

__device__ __forceinline__ void ldsm4(uint32_t* r, uint32_t addr) {
    asm volatile("ldmatrix.sync.aligned.m8n8.x4.shared.b16 {%0,%1,%2,%3}, [%4];"
        : "=r"(r[0]), "=r"(r[1]), "=r"(r[2]), "=r"(r[3]) : "r"(addr));
}
__device__ __forceinline__ void mma_f16(float* c, const uint32_t* a, const uint32_t* b) {
    asm volatile("mma.sync.aligned.m16n8k16.row.col.f32.f16.f16.f32 "
        "{%0,%1,%2,%3}, {%4,%5,%6,%7}, {%8,%9}, {%0,%1,%2,%3};"
        : "+f"(c[0]), "+f"(c[1]), "+f"(c[2]), "+f"(c[3])
        : "r"(a[0]), "r"(a[1]), "r"(a[2]), "r"(a[3]), "r"(b[0]), "r"(b[1]));
}

// ---------------- small kernels ----------------
__global__ void zero_cnt_kernel() {
    if (threadIdx.x < E_NUM) g_cnt[threadIdx.x] = 0;
}

__global__ void cvt_x_kernel(const float* __restrict__ x) {
    size_t stride = (size_t)gridDim.x * blockDim.x;
    size_t n = (size_t)N_TOK * D_DIM;
    for (size_t i = (size_t)blockIdx.x * blockDim.x + threadIdx.x; i < n; i += stride)
        g_xh[i] = __float2half_rn(x[i]);
}

// W[e][K][N] fp32 -> P[e][N][K] fp16 hi (32x32 tile transpose)
__global__ __launch_bounds__(256)
void pack_w_kernel(const float* __restrict__ W, __half* __restrict__ Ph, int K, int N) {
    __shared__ float s[32][33];
    const int k0 = blockIdx.x * 32, n0 = blockIdx.y * 32, e = blockIdx.z;
    const int tid = threadIdx.x;
    const int kk = tid >> 5, nn = tid & 31;
#pragma unroll
    for (int i = 0; i < 4; i++)
        s[kk + i * 8][nn] = W[((size_t)e * K + k0 + kk + i * 8) * N + n0 + nn];
    __syncthreads();
    const int n_r = tid >> 4;
    const int kp  = (tid & 15) * 2;
#pragma unroll
    for (int i = 0; i < 2; i++) {
        int nr = n_r + i * 16;
        __half2 hp;
        hp.x = __float2half_rn(s[kp][nr]);
        hp.y = __float2half_rn(s[kp + 1][nr]);
        size_t o = ((size_t)e * N + n0 + nr) * K + k0 + kp;
        *(__half2*)(Ph + o) = hp;
    }
}

__global__ void router_kernel(const float* __restrict__ x,
                              const float* __restrict__ Wr,
                              const float* __restrict__ br) {
    int warp = (blockIdx.x * blockDim.x + threadIdx.x) >> 5;
    int lane = threadIdx.x & 31;
    if (warp >= N_TOK) return;
    const float* xr = x + (size_t)warp * D_DIM;
    float acc[8];
#pragma unroll
    for (int e = 0; e < 8; e++) acc[e] = 0.0f;
    for (int d = lane; d < D_DIM; d += 32) {
        float xv = xr[d];
        const float4* w4 = (const float4*)(Wr + (size_t)d * E_NUM);
        float4 a = w4[0], b = w4[1];
        acc[0] += xv * a.x; acc[1] += xv * a.y; acc[2] += xv * a.z; acc[3] += xv * a.w;
        acc[4] += xv * b.x; acc[5] += xv * b.y; acc[6] += xv * b.z; acc[7] += xv * b.w;
    }
#pragma unroll
    for (int off = 16; off > 0; off >>= 1)
#pragma unroll
        for (int e = 0; e < 8; e++)
            acc[e] += __shfl_down_sync(0xffffffffu, acc[e], off);
    if (lane == 0) {
        float lg[8];
#pragma unroll
        for (int e = 0; e < 8; e++) lg[e] = acc[e] + br[e];
        int e0 = 0;
#pragma unroll
        for (int e = 1; e < 8; e++) if (lg[e] > lg[e0]) e0 = e;
        int e1 = (e0 == 0) ? 1 : 0;
#pragma unroll
        for (int e = 0; e < 8; e++)
            if (e != e0 && e != e1 && lg[e] > lg[e1]) e1 = e;
        float z  = __expf(lg[e1] - lg[e0]);
        float w0 = 1.0f / (1.0f + z);
        float w1 = z * w0;
        int p0 = atomicAdd(&g_cnt[e0], 1);
        g_tok[e0 * CAP + p0] = warp;
        int p1 = atomicAdd(&g_cnt[e1], 1);
        g_tok[e1 * CAP + p1] = warp;
        g_tslot[2 * warp]     = e0 * CAP + p0;  g_tw[2 * warp]     = w0;
        g_tslot[2 * warp + 1] = e1 * CAP + p1;  g_tw[2 * warp + 1] = w1;
    }
}

__global__ void offsets_kernel() {
    if (threadIdx.x == 0 && blockIdx.x == 0) {
        int acc = 0;
#pragma unroll
        for (int e = 0; e < E_NUM; e++) { g_off[e] = acc; acc += g_cnt[e]; }
    }
}

__global__ void combine_kernel(float* __restrict__ out) {
    int i = blockIdx.x * blockDim.x + threadIdx.x;
    int t = i >> 8;
    int j = (i & 255) << 2;
    int s0e = g_tslot[2 * t], s1e = g_tslot[2 * t + 1];
    float w0 = g_tw[2 * t], w1 = g_tw[2 * t + 1];
    size_t s0 = (size_t)g_off[s0e >> 13] + (s0e & (CAP - 1));
    size_t s1 = (size_t)g_off[s1e >> 13] + (s1e & (CAP - 1));
    float4 a = *(const float4*)(g_y + s0 * D_DIM + j);
    float4 b = *(const float4*)(g_y + s1 * D_DIM + j);
    float4 o;
    o.x = w0 * a.x + w1 * b.x;
    o.y = w0 * a.y + w1 * b.y;
    o.z = w0 * a.z + w1 * b.z;
    o.w = w0 * a.w + w1 * b.w;
    *(float4*)(out + (size_t)t * D_DIM + j) = o;
}

// ---- grouped GEMM: mma.sync fp16, single-term, 64 x 256 tile, TK=32 ----
// stage smem 76800 B * 3 = 230400... no: (64+256)*80 = 25600/stage, 3 stages = 76800 -> 2 CTA/SM
template <int PHASE, int KDIM, int NDIM>
__global__ __launch_bounds__(256)
void moe_hmma(const __half* __restrict__ Ahg,
              const __half* __restrict__ Bhg,
              const float* __restrict__ bias) {
    constexpr int C   = KDIM / TK;
    constexpr int TMV = 64;
    constexpr int WM  = TMV / 2;       // 32
    constexpr int MT  = WM / 16;       // 2
    constexpr int AHo = 0;
    constexpr int BHo = TMV * ROWB;
    constexpr uint32_t STGv = (uint32_t)(TMV + 256) * ROWB;

    const int e  = blockIdx.z;
    const int Ne = g_cnt[e];
    const int m0 = blockIdx.x * TMV;
    if (m0 >= Ne) return;
    const int n0 = blockIdx.y * 256;
    const int base = g_off[e];

    extern __shared__ __align__(128) char smem[];
    const uint32_t sb = smem_u32(smem);
    const int tid = threadIdx.x;

    // ---- A loads: thread -> row group (tid>>2), 16B seg (tid&3) ----
    const int r0 = tid >> 2;            // 0..63
    const int sg = (tid & 3) * 16;
    const char* ahp;
    {
        int rr = min(m0 + r0, Ne - 1);
        size_t i0 = (PHASE == 1) ? (size_t)g_tok[e * CAP + rr] : (size_t)(base + rr);
        ahp = (const char*)(Ahg + i0 * KDIM) + sg;
    }
    // B: 256 rows, 4 row-groups per thread
    const size_t brow = (size_t)e * NDIM + n0 + r0;
    const char* bh0 = (const char*)(Bhg + brow * KDIM) + sg;
    const uint32_t d0 = (uint32_t)r0 * ROWB + sg;

    auto issue = [&](int c) {
        if (c < C) {
            uint32_t st = sb + (uint32_t)(c % NSTAGE) * STGv;
            int cb = c * 64;   // bytes per chunk along K
            CP16(st + AHo + d0, ahp + cb);
#pragma unroll
            for (int j = 0; j < 4; j++)
                CP16(st + BHo + d0 + j * 64 * ROWB, bh0 + (size_t)j * 64 * KDIM * 2 + cb);
        }
        CP_COMMIT();
    };

    float acc[MT][8][4];
#pragma unroll
    for (int i = 0; i < MT; i++)
#pragma unroll
        for (int j = 0; j < 8; j++)
#pragma unroll
            for (int k = 0; k < 4; k++) acc[i][j][k] = 0.0f;

    const int lane = tid & 31, wid = tid >> 5;
    const int wm = (wid & 1) * WM;        // warp M offset
    const int wn = (wid >> 1) * 64;       // warp N offset
    const uint32_t a_off = (uint32_t)(wm + (lane & 15)) * ROWB + (lane >> 4) * 16;
    const uint32_t b_off = (uint32_t)(wn + (lane & 7) + ((lane >> 4) & 1) * 8) * ROWB
                         + ((lane >> 3) & 1) * 16;

    issue(0);
    issue(1);

    for (int c = 0; c < C; c++) {
        asm volatile("cp.async.wait_group 1;" ::: "memory");
        __syncthreads();
        issue(c + 2);

        const uint32_t st = sb + (uint32_t)(c % NSTAGE) * STGv;
#pragma unroll
        for (int kk = 0; kk < 2; kk++) {
            uint32_t af[4 * MT], tf[16];
#pragma unroll
            for (int tn2 = 0; tn2 < 4; tn2++)
                ldsm4(tf + tn2 * 4, st + BHo + b_off + tn2 * 16 * ROWB + kk * 32);
#pragma unroll
            for (int tm = 0; tm < MT; tm++)
                ldsm4(af + tm * 4, st + AHo + a_off + tm * 16 * ROWB + kk * 32);
#pragma unroll
            for (int tm = 0; tm < MT; tm++)
#pragma unroll
                for (int tn = 0; tn < 8; tn++)
                    mma_f16(acc[tm][tn], af + tm * 4, tf + tn * 2);
        }
    }

    // ---- epilogue ----
    const int lr_base  = wm + (lane >> 2);
    const int col_base = n0 + wn + 2 * (lane & 3);
    const float* bp = bias + (size_t)e * NDIM;
#pragma unroll
    for (int tm = 0; tm < MT; tm++) {
#pragma unroll
        for (int half = 0; half < 2; half++) {
            int gr = m0 + lr_base + tm * 16 + half * 8;
            if (gr < Ne) {
                size_t pr = (size_t)(base + gr);
#pragma unroll
                for (int tn = 0; tn < 8; tn++) {
                    int col = col_base + tn * 8;
                    float c0 = acc[tm][tn][half * 2 + 0] + __ldg(bp + col);
                    float c1 = acc[tm][tn][half * 2 + 1] + __ldg(bp + col + 1);
                    if (PHASE == 1) {
                        c0 = fmaxf(c0, 0.f);
                        c1 = fmaxf(c1, 0.f);
                        __half2 hp;
                        hp.x = __float2half_rn(c0);
                        hp.y = __float2half_rn(c1);
                        *(__half2*)(g_hh + pr * H_DIM + col) = hp;
                    } else {
                        float2 o; o.x = c0; o.y = c1;
                        *(float2*)(g_y + pr * D_DIM + col) = o;
                    }
                }
            }
        }
    }
}

// ---------------- launch ----------------
extern "C" void kernel_launch(void* const* d_in, const int* in_sizes, int n_in,
                              void* d_out, int out_size) {
    const float* x  = (const float*)d_in[0];
    const float* Wr = (const float*)d_in[1];
    const float* br = (const float*)d_in[2];
    const float* W1 = (const float*)d_in[3];
    const float* b1 = (const float*)d_in[4];
    const float* W2 = (const float*)d_in[5];
    const float* b2 = (const float*)d_in[6];
    float* out = (float*)d_out;

    const int SMEM = NSTAGE * (64 + 256) * ROWB;   // 76800 -> 2 CTA/SM

    cudaFuncSetAttribute(moe_hmma<1, D_DIM, H_DIM>,
                         cudaFuncAttributeMaxDynamicSharedMemorySize, SMEM);
    cudaFuncSetAttribute(moe_hmma<2, H_DIM, D_DIM>,
                         cudaFuncAttributeMaxDynamicSharedMemorySize, SMEM);

    __half *xh, *hh, *B1h, *B2h;
    cudaGetSymbolAddress((void**)&xh,  g_xh);
    cudaGetSymbolAddress((void**)&hh,  g_hh);
    cudaGetSymbolAddress((void**)&B1h, g_B1h); cudaGetSymbolAddress((void**)&B2h, g_B2h);

    zero_cnt_kernel<<<1, 32>>>();
    cvt_x_kernel<<<1024, 256>>>(x);
    {   // W1: K=1024, N=4096 -> [E][4096][1024]
        dim3 g(D_DIM / 32, H_DIM / 32, E_NUM);
        pack_w_kernel<<<g, 256>>>(W1, B1h, D_DIM, H_DIM);
    }
    {   // W2: K=4096, N=1024 -> [E][1024][4096]
        dim3 g(H_DIM / 32, D_DIM / 32, E_NUM);
        pack_w_kernel<<<g, 256>>>(W2, B2h, H_DIM, D_DIM);
    }
    router_kernel<<<(N_TOK * 32 + 255) / 256, 256>>>(x, Wr, br);
    offsets_kernel<<<1, 32>>>();

    {   // GEMM1: gathered x [Ne,1024] @ W1 -> relu -> h (fp16)
        dim3 g(CAP / 64, H_DIM / 256, E_NUM);
        moe_hmma<1, D_DIM, H_DIM><<<g, 256, SMEM>>>(xh, B1h, b1);
    }
    {   // GEMM2: h [Ne,4096] @ W2 -> y (+b2)
        dim3 g(CAP / 64, D_DIM / 256, E_NUM);
        moe_hmma<2, H_DIM, D_DIM><<<g, 256, SMEM>>>(hh, B2h, b2);
    }
    combine_kernel<<<N_TOK, 256>>>(out);
}

// round 13
// speedup vs baseline: 1.9056x; 1.0138x over previous
#include <cuda_runtime.h>
#include <cuda_fp16.h>
#include <math.h>
#include <stdint.h>

#define N_TOK 8192
#define D_DIM 1024
#define E_NUM 8
#define H_DIM 4096
#define CAP   8192
#define PAIRS 16384

#define TK 32            // fp16 elems per k-chunk (64 bytes per row)
#define ROWB 80          // padded SMEM row bytes (64 data + 16 pad)
#define NSTAGE 3

// ---------------- device scratch ----------------
__device__ int   g_cnt[E_NUM];
__device__ int   g_off[E_NUM];
__device__ int   g_tok[E_NUM * CAP];
__device__ float g_wt [E_NUM * CAP];

__device__ __half g_xh[(size_t)N_TOK * D_DIM];
__device__ __half g_hh[(size_t)PAIRS * H_DIM];
__device__ __half g_B1h[(size_t)E_NUM * H_DIM * D_DIM];
__device__ __half g_B2h[(size_t)E_NUM * D_DIM * H_DIM];

// ---------------- helpers ----------------
__device__ __forceinline__ uint32_t smem_u32(const void* p) {
    return (uint32_t)__cvta_generic_to_shared(p);
}
#define CP16(dst, src) \
    asm volatile("cp.async.cg.shared.global [%0], [%1], 16;" :: "r"(dst), "l"(src) : "memory")
#define CP_COMMIT() asm volatile("cp.async.commit_group;" ::: "memory")

__device__ __forceinline__ void ldsm4(uint32_t* r, uint32_t addr) {
    asm volatile("ldmatrix.sync.aligned.m8n8.x4.shared.b16 {%0,%1,%2,%3}, [%4];"
        : "=r"(r[0]), "=r"(r[1]), "=r"(r[2]), "=r"(r[3]) : "r"(addr));
}
__device__ __forceinline__ void mma_f16(float* c, const uint32_t* a, const uint32_t* b) {
    asm volatile("mma.sync.aligned.m16n8k16.row.col.f32.f16.f16.f32 "
        "{%0,%1,%2,%3}, {%4,%5,%6,%7}, {%8,%9}, {%0,%1,%2,%3};"
        : "+f"(c[0]), "+f"(c[1]), "+f"(c[2]), "+f"(c[3])
        : "r"(a[0]), "r"(a[1]), "r"(a[2]), "r"(a[3]), "r"(b[0]), "r"(b[1]));
}

// ---------------- small kernels ----------------
// zero expert counts + zero the output buffer (GEMM2 scatters atomically into it)
__global__ void zero_kernel(float* __restrict__ out, int n) {
    int i = blockIdx.x * blockDim.x + threadIdx.x;
    if (i < E_NUM) g_cnt[i] = 0;
    for (; i < n; i += gridDim.x * blockDim.x) out[i] = 0.0f;
}

// W[e][K][N] fp32 -> P[e][N][K] fp16 hi (32x32 tile transpose)
__global__ __launch_bounds__(256)
void pack_w_kernel(const float* __restrict__ W, __half* __restrict__ Ph, int K, int N) {
    __shared__ float s[32][33];
    const int k0 = blockIdx.x * 32, n0 = blockIdx.y * 32, e = blockIdx.z;
    const int tid = threadIdx.x;
    const int kk = tid >> 5, nn = tid & 31;
#pragma unroll
    for (int i = 0; i < 4; i++)
        s[kk + i * 8][nn] = W[((size_t)e * K + k0 + kk + i * 8) * N + n0 + nn];
    __syncthreads();
    const int n_r = tid >> 4;
    const int kp  = (tid & 15) * 2;
#pragma unroll
    for (int i = 0; i < 2; i++) {
        int nr = n_r + i * 16;
        __half2 hp;
        hp.x = __float2half_rn(s[kp][nr]);
        hp.y = __float2half_rn(s[kp + 1][nr]);
        size_t o = ((size_t)e * N + n0 + nr) * K + k0 + kp;
        *(__half2*)(Ph + o) = hp;
    }
}

// router + x->fp16 conversion fused (one warp per token)
__global__ void router_kernel(const float* __restrict__ x,
                              const float* __restrict__ Wr,
                              const float* __restrict__ br) {
    int warp = (blockIdx.x * blockDim.x + threadIdx.x) >> 5;
    int lane = threadIdx.x & 31;
    if (warp >= N_TOK) return;
    const float* xr = x + (size_t)warp * D_DIM;
    __half* xo = g_xh + (size_t)warp * D_DIM;
    float acc[8];
#pragma unroll
    for (int e = 0; e < 8; e++) acc[e] = 0.0f;
    for (int d = lane; d < D_DIM; d += 32) {
        float xv = xr[d];
        xo[d] = __float2half_rn(xv);
        const float4* w4 = (const float4*)(Wr + (size_t)d * E_NUM);
        float4 a = w4[0], b = w4[1];
        acc[0] += xv * a.x; acc[1] += xv * a.y; acc[2] += xv * a.z; acc[3] += xv * a.w;
        acc[4] += xv * b.x; acc[5] += xv * b.y; acc[6] += xv * b.z; acc[7] += xv * b.w;
    }
#pragma unroll
    for (int off = 16; off > 0; off >>= 1)
#pragma unroll
        for (int e = 0; e < 8; e++)
            acc[e] += __shfl_down_sync(0xffffffffu, acc[e], off);
    if (lane == 0) {
        float lg[8];
#pragma unroll
        for (int e = 0; e < 8; e++) lg[e] = acc[e] + br[e];
        int e0 = 0;
#pragma unroll
        for (int e = 1; e < 8; e++) if (lg[e] > lg[e0]) e0 = e;
        int e1 = (e0 == 0) ? 1 : 0;
#pragma unroll
        for (int e = 0; e < 8; e++)
            if (e != e0 && e != e1 && lg[e] > lg[e1]) e1 = e;
        float z  = __expf(lg[e1] - lg[e0]);
        float w0 = 1.0f / (1.0f + z);
        float w1 = z * w0;
        int p0 = atomicAdd(&g_cnt[e0], 1);
        g_tok[e0 * CAP + p0] = warp;  g_wt[e0 * CAP + p0] = w0;
        int p1 = atomicAdd(&g_cnt[e1], 1);
        g_tok[e1 * CAP + p1] = warp;  g_wt[e1 * CAP + p1] = w1;
    }
}

__global__ void offsets_kernel() {
    if (threadIdx.x == 0 && blockIdx.x == 0) {
        int acc = 0;
#pragma unroll
        for (int e = 0; e < E_NUM; e++) { g_off[e] = acc; acc += g_cnt[e]; }
    }
}

// ---- grouped GEMM: mma.sync fp16 single-term, TMV x 256 tile, TK=32 ----
// PHASE 1: TMV=128 (1 CTA/SM, high MMA:ldsm ratio) -> relu -> g_hh fp16
// PHASE 2: TMV=64  (2 CTA/SM) -> weighted atomicAdd scatter into out
template <int PHASE, int KDIM, int NDIM, int TMV>
__global__ __launch_bounds__(256)
void moe_hmma(const __half* __restrict__ Ahg,
              const __half* __restrict__ Bhg,
              const float* __restrict__ bias,
              float* __restrict__ out) {
    constexpr int C   = KDIM / TK;
    constexpr int WM  = TMV / 2;
    constexpr int MT  = WM / 16;
    constexpr int AHo = 0;
    constexpr int BHo = TMV * ROWB;
    constexpr uint32_t STGv = (uint32_t)(TMV + 256) * ROWB;

    const int e  = blockIdx.z;
    const int Ne = g_cnt[e];
    const int m0 = blockIdx.x * TMV;
    if (m0 >= Ne) return;
    const int n0 = blockIdx.y * 256;
    const int base = g_off[e];

    extern __shared__ __align__(128) char smem[];
    const uint32_t sb = smem_u32(smem);
    const int tid = threadIdx.x;

    // ---- A loads: thread -> row group (tid>>2), 16B seg (tid&3) ----
    const int r0 = tid >> 2;            // 0..63
    const int sg = (tid & 3) * 16;
    const char* ahp[TMV / 64];
#pragma unroll
    for (int j = 0; j < TMV / 64; j++) {
        int rr = min(m0 + r0 + j * 64, Ne - 1);
        size_t i0 = (PHASE == 1) ? (size_t)g_tok[e * CAP + rr] : (size_t)(base + rr);
        ahp[j] = (const char*)(Ahg + i0 * KDIM) + sg;
    }
    // B: 256 rows, 4 row-groups per thread
    const size_t brow = (size_t)e * NDIM + n0 + r0;
    const char* bh0 = (const char*)(Bhg + brow * KDIM) + sg;
    const uint32_t d0 = (uint32_t)r0 * ROWB + sg;

    auto issue = [&](int c) {
        if (c < C) {
            uint32_t st = sb + (uint32_t)(c % NSTAGE) * STGv;
            int cb = c * 64;   // bytes per chunk along K
#pragma unroll
            for (int j = 0; j < TMV / 64; j++)
                CP16(st + AHo + d0 + j * 64 * ROWB, ahp[j] + cb);
#pragma unroll
            for (int j = 0; j < 4; j++)
                CP16(st + BHo + d0 + j * 64 * ROWB, bh0 + (size_t)j * 64 * KDIM * 2 + cb);
        }
        CP_COMMIT();
    };

    float acc[MT][8][4];
#pragma unroll
    for (int i = 0; i < MT; i++)
#pragma unroll
        for (int j = 0; j < 8; j++)
#pragma unroll
            for (int k = 0; k < 4; k++) acc[i][j][k] = 0.0f;

    const int lane = tid & 31, wid = tid >> 5;
    const int wm = (wid & 1) * WM;        // warp M offset
    const int wn = (wid >> 1) * 64;       // warp N offset
    const uint32_t a_off = (uint32_t)(wm + (lane & 15)) * ROWB + (lane >> 4) * 16;
    const uint32_t b_off = (uint32_t)(wn + (lane & 7) + ((lane >> 4) & 1) * 8) * ROWB
                         + ((lane >> 3) & 1) * 16;

    issue(0);
    issue(1);

    for (int c = 0; c < C; c++) {
        asm volatile("cp.async.wait_group 1;" ::: "memory");
        __syncthreads();
        issue(c + 2);

        const uint32_t st = sb + (uint32_t)(c % NSTAGE) * STGv;
#pragma unroll
        for (int kk = 0; kk < 2; kk++) {
            uint32_t af[4 * MT], tf[16];
#pragma unroll
            for (int tn2 = 0; tn2 < 4; tn2++)
                ldsm4(tf + tn2 * 4, st + BHo + b_off + tn2 * 16 * ROWB + kk * 32);
#pragma unroll
            for (int tm = 0; tm < MT; tm++)
                ldsm4(af + tm * 4, st + AHo + a_off + tm * 16 * ROWB + kk * 32);
#pragma unroll
            for (int tm = 0; tm < MT; tm++)
#pragma unroll
                for (int tn = 0; tn < 8; tn++)
                    mma_f16(acc[tm][tn], af + tm * 4, tf + tn * 2);
        }
    }

    // ---- epilogue ----
    const int lr_base  = wm + (lane >> 2);
    const int col_base = n0 + wn + 2 * (lane & 3);
    const float* bp = bias + (size_t)e * NDIM;
#pragma unroll
    for (int tm = 0; tm < MT; tm++) {
#pragma unroll
        for (int half = 0; half < 2; half++) {
            int gr = m0 + lr_base + tm * 16 + half * 8;
            if (gr < Ne) {
                if (PHASE == 1) {
                    size_t pr = (size_t)(base + gr);
#pragma unroll
                    for (int tn = 0; tn < 8; tn++) {
                        int col = col_base + tn * 8;
                        float c0 = fmaxf(acc[tm][tn][half * 2 + 0] + __ldg(bp + col),     0.f);
                        float c1 = fmaxf(acc[tm][tn][half * 2 + 1] + __ldg(bp + col + 1), 0.f);
                        __half2 hp;
                        hp.x = __float2half_rn(c0);
                        hp.y = __float2half_rn(c1);
                        *(__half2*)(g_hh + pr * H_DIM + col) = hp;
                    }
                } else {
                    int   tok = g_tok[e * CAP + gr];
                    float w   = g_wt [e * CAP + gr];
                    float* op = out + (size_t)tok * NDIM;
#pragma unroll
                    for (int tn = 0; tn < 8; tn++) {
                        int col = col_base + tn * 8;
                        atomicAdd(op + col,     w * (acc[tm][tn][half * 2 + 0] + __ldg(bp + col)));
                        atomicAdd(op + col + 1, w * (acc[tm][tn][half * 2 + 1] + __ldg(bp + col + 1)));
                    }
                }
            }
        }
    }
}

// ---------------- launch ----------------
extern "C" void kernel_launch(void* const* d_in, const int* in_sizes, int n_in,
                              void* d_out, int out_size) {
    const float* x  = (const float*)d_in[0];
    const float* Wr = (const float*)d_in[1];
    const float* br = (const float*)d_in[2];
    const float* W1 = (const float*)d_in[3];
    const float* b1 = (const float*)d_in[4];
    const float* W2 = (const float*)d_in[5];
    const float* b2 = (const float*)d_in[6];
    float* out = (float*)d_out;

    const int SMEM1 = NSTAGE * (128 + 256) * ROWB;   // 92160 (regs limit to 1 CTA/SM)
    const int SMEM2 = NSTAGE * (64 + 256) * ROWB;    // 76800 -> 2 CTA/SM

    cudaFuncSetAttribute(moe_hmma<1, D_DIM, H_DIM, 128>,
                         cudaFuncAttributeMaxDynamicSharedMemorySize, SMEM1);
    cudaFuncSetAttribute(moe_hmma<2, H_DIM, D_DIM, 64>,
                         cudaFuncAttributeMaxDynamicSharedMemorySize, SMEM2);

    __half *xh, *hh, *B1h, *B2h;
    cudaGetSymbolAddress((void**)&xh,  g_xh);
    cudaGetSymbolAddress((void**)&hh,  g_hh);
    cudaGetSymbolAddress((void**)&B1h, g_B1h); cudaGetSymbolAddress((void**)&B2h, g_B2h);

    zero_kernel<<<1024, 256>>>(out, out_size);
    {   // W1: K=1024, N=4096 -> [E][4096][1024]
        dim3 g(D_DIM / 32, H_DIM / 32, E_NUM);
        pack_w_kernel<<<g, 256>>>(W1, B1h, D_DIM, H_DIM);
    }
    {   // W2: K=4096, N=1024 -> [E][1024][4096]
        dim3 g(H_DIM / 32, D_DIM / 32, E_NUM);
        pack_w_kernel<<<g, 256>>>(W2, B2h, H_DIM, D_DIM);
    }
    router_kernel<<<(N_TOK * 32 + 255) / 256, 256>>>(x, Wr, br);
    offsets_kernel<<<1, 32>>>();

    {   // GEMM1: gathered x [Ne,1024] @ W1 -> relu -> h (fp16); TM=128
        dim3 g(CAP / 128, H_DIM / 256, E_NUM);
        moe_hmma<1, D_DIM, H_DIM, 128><<<g, 256, SMEM1>>>(xh, B1h, b1, nullptr);
    }
    {   // GEMM2: h [Ne,4096] @ W2 -> weighted atomic scatter into out; TM=64
        dim3 g(CAP / 64, D_DIM / 256, E_NUM);
        moe_hmma<2, H_DIM, D_DIM, 64><<<g, 256, SMEM2>>>(hh, B2h, b2, out);
    }
}

// round 14
// speedup vs baseline: 1.9090x; 1.0018x over previous
#include <cuda_runtime.h>
#include <cuda_fp16.h>
#include <math.h>
#include <stdint.h>

#define N_TOK 8192
#define D_DIM 1024
#define E_NUM 8
#define H_DIM 4096
#define CAP   8192
#define PAIRS 16384

#define TK 32            // fp16 elems per k-chunk (64 bytes per row)
#define ROWB 80          // padded SMEM row bytes (64 data + 16 pad)

// ---------------- device scratch ----------------
__device__ int   g_cnt[E_NUM];
__device__ int   g_off[E_NUM];
__device__ int   g_tok[E_NUM * CAP];
__device__ float g_wt [E_NUM * CAP];

__device__ __half g_xh[(size_t)N_TOK * D_DIM];
__device__ __half g_hh[(size_t)PAIRS * H_DIM];
__device__ __half g_B1h[(size_t)E_NUM * H_DIM * D_DIM];
__device__ __half g_B2h[(size_t)E_NUM * D_DIM * H_DIM];

// ---------------- helpers ----------------
__device__ __forceinline__ uint32_t smem_u32(const void* p) {
    return (uint32_t)__cvta_generic_to_shared(p);
}
#define CP16(dst, src) \
    asm volatile("cp.async.cg.shared.global [%0], [%1], 16;" :: "r"(dst), "l"(src) : "memory")
#define CP_COMMIT() asm volatile("cp.async.commit_group;" ::: "memory")

__device__ __forceinline__ void ldsm4(uint32_t* r, uint32_t addr) {
    asm volatile("ldmatrix.sync.aligned.m8n8.x4.shared.b16 {%0,%1,%2,%3}, [%4];"
        : "=r"(r[0]), "=r"(r[1]), "=r"(r[2]), "=r"(r[3]) : "r"(addr));
}
__device__ __forceinline__ void mma_f16(float* c, const uint32_t* a, const uint32_t* b) {
    asm volatile("mma.sync.aligned.m16n8k16.row.col.f32.f16.f16.f32 "
        "{%0,%1,%2,%3}, {%4,%5,%6,%7}, {%8,%9}, {%0,%1,%2,%3};"
        : "+f"(c[0]), "+f"(c[1]), "+f"(c[2]), "+f"(c[3])
        : "r"(a[0]), "r"(a[1]), "r"(a[2]), "r"(a[3]), "r"(b[0]), "r"(b[1]));
}

// ---------------- small kernels ----------------
// zero expert counts + zero the output buffer (GEMM2 scatters atomically into it)
__global__ void zero_kernel(float* __restrict__ out, int n) {
    int i = blockIdx.x * blockDim.x + threadIdx.x;
    if (i < E_NUM) g_cnt[i] = 0;
    for (; i < n; i += gridDim.x * blockDim.x) out[i] = 0.0f;
}

// W[e][K][N] fp32 -> P[e][N][K] fp16 hi (32x32 tile transpose)
__global__ __launch_bounds__(256)
void pack_w_kernel(const float* __restrict__ W, __half* __restrict__ Ph, int K, int N) {
    __shared__ float s[32][33];
    const int k0 = blockIdx.x * 32, n0 = blockIdx.y * 32, e = blockIdx.z;
    const int tid = threadIdx.x;
    const int kk = tid >> 5, nn = tid & 31;
#pragma unroll
    for (int i = 0; i < 4; i++)
        s[kk + i * 8][nn] = W[((size_t)e * K + k0 + kk + i * 8) * N + n0 + nn];
    __syncthreads();
    const int n_r = tid >> 4;
    const int kp  = (tid & 15) * 2;
#pragma unroll
    for (int i = 0; i < 2; i++) {
        int nr = n_r + i * 16;
        __half2 hp;
        hp.x = __float2half_rn(s[kp][nr]);
        hp.y = __float2half_rn(s[kp + 1][nr]);
        size_t o = ((size_t)e * N + n0 + nr) * K + k0 + kp;
        *(__half2*)(Ph + o) = hp;
    }
}

// router + x->fp16 conversion fused (one warp per token)
__global__ void router_kernel(const float* __restrict__ x,
                              const float* __restrict__ Wr,
                              const float* __restrict__ br) {
    int warp = (blockIdx.x * blockDim.x + threadIdx.x) >> 5;
    int lane = threadIdx.x & 31;
    if (warp >= N_TOK) return;
    const float* xr = x + (size_t)warp * D_DIM;
    __half* xo = g_xh + (size_t)warp * D_DIM;
    float acc[8];
#pragma unroll
    for (int e = 0; e < 8; e++) acc[e] = 0.0f;
    for (int d = lane; d < D_DIM; d += 32) {
        float xv = xr[d];
        xo[d] = __float2half_rn(xv);
        const float4* w4 = (const float4*)(Wr + (size_t)d * E_NUM);
        float4 a = w4[0], b = w4[1];
        acc[0] += xv * a.x; acc[1] += xv * a.y; acc[2] += xv * a.z; acc[3] += xv * a.w;
        acc[4] += xv * b.x; acc[5] += xv * b.y; acc[6] += xv * b.z; acc[7] += xv * b.w;
    }
#pragma unroll
    for (int off = 16; off > 0; off >>= 1)
#pragma unroll
        for (int e = 0; e < 8; e++)
            acc[e] += __shfl_down_sync(0xffffffffu, acc[e], off);
    if (lane == 0) {
        float lg[8];
#pragma unroll
        for (int e = 0; e < 8; e++) lg[e] = acc[e] + br[e];
        int e0 = 0;
#pragma unroll
        for (int e = 1; e < 8; e++) if (lg[e] > lg[e0]) e0 = e;
        int e1 = (e0 == 0) ? 1 : 0;
#pragma unroll
        for (int e = 0; e < 8; e++)
            if (e != e0 && e != e1 && lg[e] > lg[e1]) e1 = e;
        float z  = __expf(lg[e1] - lg[e0]);
        float w0 = 1.0f / (1.0f + z);
        float w1 = z * w0;
        int p0 = atomicAdd(&g_cnt[e0], 1);
        g_tok[e0 * CAP + p0] = warp;  g_wt[e0 * CAP + p0] = w0;
        int p1 = atomicAdd(&g_cnt[e1], 1);
        g_tok[e1 * CAP + p1] = warp;  g_wt[e1 * CAP + p1] = w1;
    }
}

__global__ void offsets_kernel() {
    if (threadIdx.x == 0 && blockIdx.x == 0) {
        int acc = 0;
#pragma unroll
        for (int e = 0; e < E_NUM; e++) { g_off[e] = acc; acc += g_cnt[e]; }
    }
}

// ---- grouped GEMM: mma.sync fp16 single-term, 64 x 256 tile, TK=32 ----
// PHASE 1 (NST=3): -> relu -> g_hh fp16
// PHASE 2 (NST=4): -> weighted atomicAdd scatter into out
template <int PHASE, int KDIM, int NDIM, int NST>
__global__ __launch_bounds__(256)
void moe_hmma(const __half* __restrict__ Ahg,
              const __half* __restrict__ Bhg,
              const float* __restrict__ bias,
              float* __restrict__ out) {
    constexpr int C   = KDIM / TK;
    constexpr int TMV = 64;
    constexpr int WM  = 32;
    constexpr int MT  = 2;
    constexpr int AHo = 0;
    constexpr int BHo = TMV * ROWB;
    constexpr uint32_t STGv = (uint32_t)(TMV + 256) * ROWB;

    const int e  = blockIdx.z;
    const int Ne = g_cnt[e];
    const int m0 = blockIdx.x * TMV;
    if (m0 >= Ne) return;
    const int n0 = blockIdx.y * 256;
    const int base = g_off[e];

    extern __shared__ __align__(128) char smem[];
    const uint32_t sb = smem_u32(smem);
    const int tid = threadIdx.x;

    // ---- A loads: thread -> row group (tid>>2), 16B seg (tid&3) ----
    const int r0 = tid >> 2;            // 0..63
    const int sg = (tid & 3) * 16;
    const char* ahp;
    {
        int rr = min(m0 + r0, Ne - 1);
        size_t i0 = (PHASE == 1) ? (size_t)g_tok[e * CAP + rr] : (size_t)(base + rr);
        ahp = (const char*)(Ahg + i0 * KDIM) + sg;
    }
    // B: 256 rows, 4 row-groups per thread
    const size_t brow = (size_t)e * NDIM + n0 + r0;
    const char* bh0 = (const char*)(Bhg + brow * KDIM) + sg;
    const uint32_t d0 = (uint32_t)r0 * ROWB + sg;

    auto issue = [&](int c) {
        if (c < C) {
            uint32_t st = sb + (uint32_t)(c % NST) * STGv;
            int cb = c * 64;   // bytes per chunk along K
            CP16(st + AHo + d0, ahp + cb);
#pragma unroll
            for (int j = 0; j < 4; j++)
                CP16(st + BHo + d0 + j * 64 * ROWB, bh0 + (size_t)j * 64 * KDIM * 2 + cb);
        }
        CP_COMMIT();
    };

    float acc[MT][8][4];
#pragma unroll
    for (int i = 0; i < MT; i++)
#pragma unroll
        for (int j = 0; j < 8; j++)
#pragma unroll
            for (int k = 0; k < 4; k++) acc[i][j][k] = 0.0f;

    const int lane = tid & 31, wid = tid >> 5;
    const int wm = (wid & 1) * WM;        // warp M offset
    const int wn = (wid >> 1) * 64;       // warp N offset
    const uint32_t a_off = (uint32_t)(wm + (lane & 15)) * ROWB + (lane >> 4) * 16;
    const uint32_t b_off = (uint32_t)(wn + (lane & 7) + ((lane >> 4) & 1) * 8) * ROWB
                         + ((lane >> 3) & 1) * 16;

#pragma unroll
    for (int p = 0; p < NST - 1; p++) issue(p);

    for (int c = 0; c < C; c++) {
        asm volatile("cp.async.wait_group %0;" :: "n"(NST - 2) : "memory");
        __syncthreads();
        issue(c + NST - 1);

        const uint32_t st = sb + (uint32_t)(c % NST) * STGv;
#pragma unroll
        for (int kk = 0; kk < 2; kk++) {
            uint32_t af[4 * MT], tf[16];
#pragma unroll
            for (int tn2 = 0; tn2 < 4; tn2++)
                ldsm4(tf + tn2 * 4, st + BHo + b_off + tn2 * 16 * ROWB + kk * 32);
#pragma unroll
            for (int tm = 0; tm < MT; tm++)
                ldsm4(af + tm * 4, st + AHo + a_off + tm * 16 * ROWB + kk * 32);
#pragma unroll
            for (int tm = 0; tm < MT; tm++)
#pragma unroll
                for (int tn = 0; tn < 8; tn++)
                    mma_f16(acc[tm][tn], af + tm * 4, tf + tn * 2);
        }
    }

    // ---- epilogue ----
    const int lr_base  = wm + (lane >> 2);
    const int col_base = n0 + wn + 2 * (lane & 3);
    const float* bp = bias + (size_t)e * NDIM;
#pragma unroll
    for (int tm = 0; tm < MT; tm++) {
#pragma unroll
        for (int half = 0; half < 2; half++) {
            int gr = m0 + lr_base + tm * 16 + half * 8;
            if (gr < Ne) {
                if (PHASE == 1) {
                    size_t pr = (size_t)(base + gr);
#pragma unroll
                    for (int tn = 0; tn < 8; tn++) {
                        int col = col_base + tn * 8;
                        float c0 = fmaxf(acc[tm][tn][half * 2 + 0] + __ldg(bp + col),     0.f);
                        float c1 = fmaxf(acc[tm][tn][half * 2 + 1] + __ldg(bp + col + 1), 0.f);
                        __half2 hp;
                        hp.x = __float2half_rn(c0);
                        hp.y = __float2half_rn(c1);
                        *(__half2*)(g_hh + pr * H_DIM + col) = hp;
                    }
                } else {
                    int   tok = g_tok[e * CAP + gr];
                    float w   = g_wt [e * CAP + gr];
                    float* op = out + (size_t)tok * NDIM;
#pragma unroll
                    for (int tn = 0; tn < 8; tn++) {
                        int col = col_base + tn * 8;
                        atomicAdd(op + col,     w * (acc[tm][tn][half * 2 + 0] + __ldg(bp + col)));
                        atomicAdd(op + col + 1, w * (acc[tm][tn][half * 2 + 1] + __ldg(bp + col + 1)));
                    }
                }
            }
        }
    }
}

// ---------------- launch ----------------
extern "C" void kernel_launch(void* const* d_in, const int* in_sizes, int n_in,
                              void* d_out, int out_size) {
    const float* x  = (const float*)d_in[0];
    const float* Wr = (const float*)d_in[1];
    const float* br = (const float*)d_in[2];
    const float* W1 = (const float*)d_in[3];
    const float* b1 = (const float*)d_in[4];
    const float* W2 = (const float*)d_in[5];
    const float* b2 = (const float*)d_in[6];
    float* out = (float*)d_out;

    const int SMEM1 = 3 * (64 + 256) * ROWB;   // 76800 -> 2 CTA/SM
    const int SMEM2 = 4 * (64 + 256) * ROWB;   // 102400 -> 2 CTA/SM

    cudaFuncSetAttribute(moe_hmma<1, D_DIM, H_DIM, 3>,
                         cudaFuncAttributeMaxDynamicSharedMemorySize, SMEM1);
    cudaFuncSetAttribute(moe_hmma<2, H_DIM, D_DIM, 4>,
                         cudaFuncAttributeMaxDynamicSharedMemorySize, SMEM2);

    __half *xh, *hh, *B1h, *B2h;
    cudaGetSymbolAddress((void**)&xh,  g_xh);
    cudaGetSymbolAddress((void**)&hh,  g_hh);
    cudaGetSymbolAddress((void**)&B1h, g_B1h); cudaGetSymbolAddress((void**)&B2h, g_B2h);

    zero_kernel<<<1024, 256>>>(out, out_size);
    {   // W1: K=1024, N=4096 -> [E][4096][1024]
        dim3 g(D_DIM / 32, H_DIM / 32, E_NUM);
        pack_w_kernel<<<g, 256>>>(W1, B1h, D_DIM, H_DIM);
    }
    {   // W2: K=4096, N=1024 -> [E][1024][4096]
        dim3 g(H_DIM / 32, D_DIM / 32, E_NUM);
        pack_w_kernel<<<g, 256>>>(W2, B2h, H_DIM, D_DIM);
    }
    router_kernel<<<(N_TOK * 32 + 255) / 256, 256>>>(x, Wr, br);
    offsets_kernel<<<1, 32>>>();

    {   // GEMM1: gathered x [Ne,1024] @ W1 -> relu -> h (fp16); TM=64, 2 CTA/SM
        dim3 g(CAP / 64, H_DIM / 256, E_NUM);
        moe_hmma<1, D_DIM, H_DIM, 3><<<g, 256, SMEM1>>>(xh, B1h, b1, nullptr);
    }
    {   // GEMM2: h [Ne,4096] @ W2 -> weighted atomic scatter into out; TM=64, 4 stages
        dim3 g(CAP / 64, D_DIM / 256, E_NUM);
        moe_hmma<2, H_DIM, D_DIM, 4><<<g, 256, SMEM2>>>(hh, B2h, b2, out);
    }
}

// round 15
// speedup vs baseline: 2.1115x; 1.1061x over previous
#include <cuda_runtime.h>
#include <cuda_fp16.h>
#include <math.h>
#include <stdint.h>

#define N_TOK 8192
#define D_DIM 1024
#define E_NUM 8
#define H_DIM 4096
#define CAP   8192
#define PAIRS 16384

#define TK 32            // fp16 elems per k-chunk (64 bytes per row)
#define ROWB 80          // padded SMEM row bytes (64 data + 16 pad)

// ---------------- device scratch ----------------
__device__ int   g_cnt[E_NUM];
__device__ int   g_off[E_NUM];
__device__ int   g_tok[E_NUM * CAP];
__device__ float g_wt [E_NUM * CAP];

__device__ __half g_xh[(size_t)N_TOK * D_DIM];
__device__ __half g_hh[(size_t)PAIRS * H_DIM];
__device__ __half g_B1h[(size_t)E_NUM * H_DIM * D_DIM];
__device__ __half g_B2h[(size_t)E_NUM * D_DIM * H_DIM];

// ---------------- helpers ----------------
__device__ __forceinline__ uint32_t smem_u32(const void* p) {
    return (uint32_t)__cvta_generic_to_shared(p);
}
#define CP16(dst, src) \
    asm volatile("cp.async.cg.shared.global [%0], [%1], 16;" :: "r"(dst), "l"(src) : "memory")
#define CP_COMMIT() asm volatile("cp.async.commit_group;" ::: "memory")

__device__ __forceinline__ void ldsm4(uint32_t* r, uint32_t addr) {
    asm volatile("ldmatrix.sync.aligned.m8n8.x4.shared.b16 {%0,%1,%2,%3}, [%4];"
        : "=r"(r[0]), "=r"(r[1]), "=r"(r[2]), "=r"(r[3]) : "r"(addr));
}
__device__ __forceinline__ void mma_f16(float* c, const uint32_t* a, const uint32_t* b) {
    asm volatile("mma.sync.aligned.m16n8k16.row.col.f32.f16.f16.f32 "
        "{%0,%1,%2,%3}, {%4,%5,%6,%7}, {%8,%9}, {%0,%1,%2,%3};"
        : "+f"(c[0]), "+f"(c[1]), "+f"(c[2]), "+f"(c[3])
        : "r"(a[0]), "r"(a[1]), "r"(a[2]), "r"(a[3]), "r"(b[0]), "r"(b[1]));
}

// ---------------- small kernels ----------------
__global__ void zero_kernel(float* __restrict__ out, int n) {
    int i = blockIdx.x * blockDim.x + threadIdx.x;
    if (i < E_NUM) g_cnt[i] = 0;
    for (; i < n; i += gridDim.x * blockDim.x) out[i] = 0.0f;
}

// W[e][K][N] fp32 -> P[e][N][K] fp16 hi (32x32 tile transpose)
__global__ __launch_bounds__(256)
void pack_w_kernel(const float* __restrict__ W, __half* __restrict__ Ph, int K, int N) {
    __shared__ float s[32][33];
    const int k0 = blockIdx.x * 32, n0 = blockIdx.y * 32, e = blockIdx.z;
    const int tid = threadIdx.x;
    const int kk = tid >> 5, nn = tid & 31;
#pragma unroll
    for (int i = 0; i < 4; i++)
        s[kk + i * 8][nn] = W[((size_t)e * K + k0 + kk + i * 8) * N + n0 + nn];
    __syncthreads();
    const int n_r = tid >> 4;
    const int kp  = (tid & 15) * 2;
#pragma unroll
    for (int i = 0; i < 2; i++) {
        int nr = n_r + i * 16;
        __half2 hp;
        hp.x = __float2half_rn(s[kp][nr]);
        hp.y = __float2half_rn(s[kp + 1][nr]);
        size_t o = ((size_t)e * N + n0 + nr) * K + k0 + kp;
        *(__half2*)(Ph + o) = hp;
    }
}

// router + x->fp16 conversion fused (one warp per token)
__global__ void router_kernel(const float* __restrict__ x,
                              const float* __restrict__ Wr,
                              const float* __restrict__ br) {
    int warp = (blockIdx.x * blockDim.x + threadIdx.x) >> 5;
    int lane = threadIdx.x & 31;
    if (warp >= N_TOK) return;
    const float* xr = x + (size_t)warp * D_DIM;
    __half* xo = g_xh + (size_t)warp * D_DIM;
    float acc[8];
#pragma unroll
    for (int e = 0; e < 8; e++) acc[e] = 0.0f;
    for (int d = lane; d < D_DIM; d += 32) {
        float xv = xr[d];
        xo[d] = __float2half_rn(xv);
        const float4* w4 = (const float4*)(Wr + (size_t)d * E_NUM);
        float4 a = w4[0], b = w4[1];
        acc[0] += xv * a.x; acc[1] += xv * a.y; acc[2] += xv * a.z; acc[3] += xv * a.w;
        acc[4] += xv * b.x; acc[5] += xv * b.y; acc[6] += xv * b.z; acc[7] += xv * b.w;
    }
#pragma unroll
    for (int off = 16; off > 0; off >>= 1)
#pragma unroll
        for (int e = 0; e < 8; e++)
            acc[e] += __shfl_down_sync(0xffffffffu, acc[e], off);
    if (lane == 0) {
        float lg[8];
#pragma unroll
        for (int e = 0; e < 8; e++) lg[e] = acc[e] + br[e];
        int e0 = 0;
#pragma unroll
        for (int e = 1; e < 8; e++) if (lg[e] > lg[e0]) e0 = e;
        int e1 = (e0 == 0) ? 1 : 0;
#pragma unroll
        for (int e = 0; e < 8; e++)
            if (e != e0 && e != e1 && lg[e] > lg[e1]) e1 = e;
        float z  = __expf(lg[e1] - lg[e0]);
        float w0 = 1.0f / (1.0f + z);
        float w1 = z * w0;
        int p0 = atomicAdd(&g_cnt[e0], 1);
        g_tok[e0 * CAP + p0] = warp;  g_wt[e0 * CAP + p0] = w0;
        int p1 = atomicAdd(&g_cnt[e1], 1);
        g_tok[e1 * CAP + p1] = warp;  g_wt[e1 * CAP + p1] = w1;
    }
}

__global__ void offsets_kernel() {
    if (threadIdx.x == 0 && blockIdx.x == 0) {
        int acc = 0;
#pragma unroll
        for (int e = 0; e < E_NUM; e++) { g_off[e] = acc; acc += g_cnt[e]; }
    }
}

// ---- grouped GEMM: mma.sync fp16 single-term, 128 x 256 tile, 512 threads ----
// 16 warps, warp tile 32x64 -> 64 acc regs/thread; B traffic halved vs TM=64.
// PHASE 1 (NST=3): -> relu -> g_hh fp16
// PHASE 2 (NST=4): -> weighted atomicAdd scatter into out
template <int PHASE, int KDIM, int NDIM, int NST>
__global__ __launch_bounds__(512, 1)
void moe_hmma(const __half* __restrict__ Ahg,
              const __half* __restrict__ Bhg,
              const float* __restrict__ bias,
              float* __restrict__ out) {
    constexpr int C   = KDIM / TK;
    constexpr int TMV = 128;
    constexpr int MT  = 2;             // warp M tile 32
    constexpr int AHo = 0;
    constexpr int BHo = TMV * ROWB;
    constexpr uint32_t STGv = (uint32_t)(TMV + 256) * ROWB;   // 30720

    const int e  = blockIdx.z;
    const int Ne = g_cnt[e];
    const int m0 = blockIdx.x * TMV;
    if (m0 >= Ne) return;
    const int n0 = blockIdx.y * 256;
    const int base = g_off[e];

    extern __shared__ __align__(128) char smem[];
    const uint32_t sb = smem_u32(smem);
    const int tid = threadIdx.x;

    // ---- A loads: 128 rows, thread -> row (tid>>2), 16B seg (tid&3) ----
    const int ar = tid >> 2;            // 0..127
    const int asg = (tid & 3) * 16;
    const char* ahp;
    {
        int rr = min(m0 + ar, Ne - 1);
        size_t i0 = (PHASE == 1) ? (size_t)g_tok[e * CAP + rr] : (size_t)(base + rr);
        ahp = (const char*)(Ahg + i0 * KDIM) + asg;
    }
    const uint32_t dA = (uint32_t)ar * ROWB + asg;

    // ---- B loads: 256 rows, thread -> row (tid>>1), 2 x 16B segs ----
    const int brr = tid >> 1;           // 0..255
    const int bsg = (tid & 1) * 32;
    const char* bh0 = (const char*)(Bhg + ((size_t)e * NDIM + n0 + brr) * KDIM) + bsg;
    const uint32_t dB = (uint32_t)brr * ROWB + bsg;

    auto issue = [&](int c) {
        if (c < C) {
            uint32_t st = sb + (uint32_t)(c % NST) * STGv;
            int cb = c * 64;   // bytes per chunk along K
            CP16(st + AHo + dA, ahp + cb);
            CP16(st + BHo + dB,      bh0 + cb);
            CP16(st + BHo + dB + 16, bh0 + cb + 16);
        }
        CP_COMMIT();
    };

    float acc[MT][8][4];
#pragma unroll
    for (int i = 0; i < MT; i++)
#pragma unroll
        for (int j = 0; j < 8; j++)
#pragma unroll
            for (int k = 0; k < 4; k++) acc[i][j][k] = 0.0f;

    const int lane = tid & 31, wid = tid >> 5;
    const int wm = (wid & 3) * 32;        // warp M offset (4 slots x 32 = 128)
    const int wn = (wid >> 2) * 64;       // warp N offset (4 slots x 64 = 256)
    const uint32_t a_off = (uint32_t)(wm + (lane & 15)) * ROWB + (lane >> 4) * 16;
    const uint32_t b_off = (uint32_t)(wn + (lane & 7) + ((lane >> 4) & 1) * 8) * ROWB
                         + ((lane >> 3) & 1) * 16;

#pragma unroll
    for (int p = 0; p < NST - 1; p++) issue(p);

    for (int c = 0; c < C; c++) {
        asm volatile("cp.async.wait_group %0;" :: "n"(NST - 2) : "memory");
        __syncthreads();
        issue(c + NST - 1);

        const uint32_t st = sb + (uint32_t)(c % NST) * STGv;
#pragma unroll
        for (int kk = 0; kk < 2; kk++) {
            uint32_t af[4 * MT], tf[16];
#pragma unroll
            for (int tn2 = 0; tn2 < 4; tn2++)
                ldsm4(tf + tn2 * 4, st + BHo + b_off + tn2 * 16 * ROWB + kk * 32);
#pragma unroll
            for (int tm = 0; tm < MT; tm++)
                ldsm4(af + tm * 4, st + AHo + a_off + tm * 16 * ROWB + kk * 32);
#pragma unroll
            for (int tm = 0; tm < MT; tm++)
#pragma unroll
                for (int tn = 0; tn < 8; tn++)
                    mma_f16(acc[tm][tn], af + tm * 4, tf + tn * 2);
        }
    }

    // ---- epilogue ----
    const int lr_base  = wm + (lane >> 2);
    const int col_base = n0 + wn + 2 * (lane & 3);
    const float* bp = bias + (size_t)e * NDIM;
#pragma unroll
    for (int tm = 0; tm < MT; tm++) {
#pragma unroll
        for (int half = 0; half < 2; half++) {
            int gr = m0 + lr_base + tm * 16 + half * 8;
            if (gr < Ne) {
                if (PHASE == 1) {
                    size_t pr = (size_t)(base + gr);
#pragma unroll
                    for (int tn = 0; tn < 8; tn++) {
                        int col = col_base + tn * 8;
                        float c0 = fmaxf(acc[tm][tn][half * 2 + 0] + __ldg(bp + col),     0.f);
                        float c1 = fmaxf(acc[tm][tn][half * 2 + 1] + __ldg(bp + col + 1), 0.f);
                        __half2 hp;
                        hp.x = __float2half_rn(c0);
                        hp.y = __float2half_rn(c1);
                        *(__half2*)(g_hh + pr * H_DIM + col) = hp;
                    }
                } else {
                    int   tok = g_tok[e * CAP + gr];
                    float w   = g_wt [e * CAP + gr];
                    float* op = out + (size_t)tok * NDIM;
#pragma unroll
                    for (int tn = 0; tn < 8; tn++) {
                        int col = col_base + tn * 8;
                        atomicAdd(op + col,     w * (acc[tm][tn][half * 2 + 0] + __ldg(bp + col)));
                        atomicAdd(op + col + 1, w * (acc[tm][tn][half * 2 + 1] + __ldg(bp + col + 1)));
                    }
                }
            }
        }
    }
}

// ---------------- launch ----------------
extern "C" void kernel_launch(void* const* d_in, const int* in_sizes, int n_in,
                              void* d_out, int out_size) {
    const float* x  = (const float*)d_in[0];
    const float* Wr = (const float*)d_in[1];
    const float* br = (const float*)d_in[2];
    const float* W1 = (const float*)d_in[3];
    const float* b1 = (const float*)d_in[4];
    const float* W2 = (const float*)d_in[5];
    const float* b2 = (const float*)d_in[6];
    float* out = (float*)d_out;

    const int SMEM1 = 3 * (128 + 256) * ROWB;   // 92160
    const int SMEM2 = 4 * (128 + 256) * ROWB;   // 122880

    cudaFuncSetAttribute(moe_hmma<1, D_DIM, H_DIM, 3>,
                         cudaFuncAttributeMaxDynamicSharedMemorySize, SMEM1);
    cudaFuncSetAttribute(moe_hmma<2, H_DIM, D_DIM, 4>,
                         cudaFuncAttributeMaxDynamicSharedMemorySize, SMEM2);

    __half *xh, *hh, *B1h, *B2h;
    cudaGetSymbolAddress((void**)&xh,  g_xh);
    cudaGetSymbolAddress((void**)&hh,  g_hh);
    cudaGetSymbolAddress((void**)&B1h, g_B1h); cudaGetSymbolAddress((void**)&B2h, g_B2h);

    zero_kernel<<<1024, 256>>>(out, out_size);
    {   // W1: K=1024, N=4096 -> [E][4096][1024]
        dim3 g(D_DIM / 32, H_DIM / 32, E_NUM);
        pack_w_kernel<<<g, 256>>>(W1, B1h, D_DIM, H_DIM);
    }
    {   // W2: K=4096, N=1024 -> [E][1024][4096]
        dim3 g(H_DIM / 32, D_DIM / 32, E_NUM);
        pack_w_kernel<<<g, 256>>>(W2, B2h, H_DIM, D_DIM);
    }
    router_kernel<<<(N_TOK * 32 + 255) / 256, 256>>>(x, Wr, br);
    offsets_kernel<<<1, 32>>>();

    {   // GEMM1: gathered x [Ne,1024] @ W1 -> relu -> h (fp16); TM=128, 512 thr
        dim3 g(CAP / 128, H_DIM / 256, E_NUM);
        moe_hmma<1, D_DIM, H_DIM, 3><<<g, 512, SMEM1>>>(xh, B1h, b1, nullptr);
    }
    {   // GEMM2: h [Ne,4096] @ W2 -> weighted atomic scatter; TM=128, 512 thr
        dim3 g(CAP / 128, D_DIM / 256, E_NUM);
        moe_hmma<2, H_DIM, D_DIM, 4><<<g, 512, SMEM2>>>(hh, B2h, b2, out);
    }
}